// round 8
// baseline (speedup 1.0000x reference)
#include <cuda_runtime.h>
#include <math.h>
#include <stdint.h>

// Problem constants
#define B_  256
#define T_  200
#define E_  584
#define H_  8
#define HS_ 73
#define BH_ (B_*H_)      // 2048
#define M_  (B_*T_)      // 51200

// Scratch (allocation-free rule: __device__ globals)
__device__ float g_q[BH_*T_*HS_];
__device__ float g_k[BH_*T_*HS_];
__device__ float g_v[BH_*T_*HS_];
__device__ float g_att[M_*E_];

__device__ __forceinline__ uint32_t f2tf32(float f) {
    uint32_t r;
    asm("cvt.rna.tf32.f32 %0, %1;" : "=r"(r) : "f"(f));
    return r;
}

__device__ __forceinline__ void mma_tf32(float c[4],
                                         uint32_t a0, uint32_t a1, uint32_t a2, uint32_t a3,
                                         uint32_t b0, uint32_t b1) {
    asm volatile(
        "mma.sync.aligned.m16n8k8.row.col.f32.tf32.tf32.f32 "
        "{%0,%1,%2,%3}, {%4,%5,%6,%7}, {%8,%9}, {%0,%1,%2,%3};"
        : "+f"(c[0]), "+f"(c[1]), "+f"(c[2]), "+f"(c[3])
        : "r"(a0), "r"(a1), "r"(a2), "r"(a3), "r"(b0), "r"(b1));
}

__device__ __forceinline__ uint32_t s2u(const void* p) {
    return (uint32_t)__cvta_generic_to_shared(p);
}
__device__ __forceinline__ void cp16(uint32_t d, const void* s, bool v) {
    asm volatile("cp.async.ca.shared.global [%0], [%1], 16, %2;"
                 :: "r"(d), "l"(s), "r"(v ? 16 : 0));
}
__device__ __forceinline__ void cp_commit() {
    asm volatile("cp.async.commit_group;");
}
__device__ __forceinline__ void cp_wait1() {
    asm volatile("cp.async.wait_group 1;");
}
__device__ __forceinline__ void named_bar(int id, int cnt) {
    asm volatile("bar.sync %0, %1;" :: "r"(id), "r"(cnt) : "memory");
}

// ---------------------------------------------------------------------------
// TF32 tensor-core GEMM v4:  C[m,n] = sum_k A[m,k] * B[n,k]
// CTA tile 128x128, BK=16, 128 threads (4 warps as 2m x 2n), warp tile 64x64.
// cp.async 3-stage pipeline; raw f32 in smem (pitch 20); cvt on fragment load.
// MODE 0: qkv projection  (A = x;     scatter to g_q/g_k/g_v)
// MODE 1: out projection  (A = g_att; +bias -> out)
// ---------------------------------------------------------------------------
#define ROWP   20
#define BK     16
#define STAGES 3
#define NSTG   37          // ceil(584/16)
#define TILE_WORDS (128*ROWP)
#define GEMM_SMEM (STAGES*2*TILE_WORDS*4)

template<int MODE>
__global__ __launch_bounds__(128)
void gemm_tf32(const float* __restrict__ Aarg,
               const float* __restrict__ B0,
               const float* __restrict__ B1,
               const float* __restrict__ B2,
               const float* __restrict__ bias,
               float* __restrict__ out)
{
    extern __shared__ float gsm[];
    float* As = gsm;                       // [STAGES][TILE_WORDS]
    float* Bs = gsm + STAGES * TILE_WORDS; // [STAGES][TILE_WORDS]

    const float* A = (MODE == 0) ? Aarg : (const float*)g_att;

    const int tid  = threadIdx.x;          // 0..127
    const int lane = tid & 31;
    const int w    = tid >> 5;             // 0..3
    const int g    = lane >> 2;
    const int c    = lane & 3;
    const int wm   = w & 1;                // 2 m-warps, 64 rows each
    const int wn   = w >> 1;               // 2 n-warps, 64 cols each

    const int m0 = blockIdx.y * 128;
    const int n0 = blockIdx.x * 128;

    float acc[4][8][4];
#pragma unroll
    for (int mi = 0; mi < 4; mi++)
#pragma unroll
        for (int ni = 0; ni < 8; ni++)
#pragma unroll
            for (int r = 0; r < 4; r++) acc[mi][ni][r] = 0.f;

    // staging: thread owns tile row `tid`, loads 4 x 16B per tile per stage
    const float* aptr = A + (size_t)(m0 + tid) * E_;

    const float* bptr;
    bool bval;
    {
        int gn = n0 + tid;
        if (MODE == 0) {
            bval = gn < 3 * E_;
            int s = gn / E_; if (s > 2) s = 2;
            int l = bval ? gn - s * E_ : 0;
            const float* W = (s == 0) ? B0 : ((s == 1) ? B1 : B2);
            bptr = W + (size_t)l * E_;
        } else {
            bval = gn < E_;
            bptr = B0 + (size_t)(bval ? gn : 0) * E_;
        }
    }

    const uint32_t a_s0 = s2u(&As[tid * ROWP]);
    const uint32_t b_s0 = s2u(&Bs[tid * ROWP]);
    const uint32_t stage_bytes = TILE_WORDS * 4;

    auto issue = [&](int s) {
        if (s < NSTG) {
            const int k0 = s * BK;
            const int slot = s % STAGES;
            const uint32_t ad = a_s0 + slot * stage_bytes;
            const uint32_t bd = b_s0 + slot * stage_bytes;
#pragma unroll
            for (int j = 0; j < 4; j++) {
                const bool v = (k0 + j * 4) < E_;
                cp16(ad + j * 16, aptr + k0 + j * 4, v);
                cp16(bd + j * 16, bptr + k0 + j * 4, v && bval);
            }
        }
        cp_commit();
    };

    issue(0);
    issue(1);

#pragma unroll 1
    for (int s = 0; s < NSTG; s++) {
        cp_wait1();
        __syncthreads();
        issue(s + 2);

        const float* as = As + (s % STAGES) * TILE_WORDS;
        const float* bs = Bs + (s % STAGES) * TILE_WORDS;

#pragma unroll
        for (int ks = 0; ks < BK; ks += 8) {
            uint32_t af[4][4], bf[8][2];
#pragma unroll
            for (int mi = 0; mi < 4; mi++) {
                const int r0 = wm * 64 + mi * 16 + g;
                af[mi][0] = f2tf32(as[r0       * ROWP + ks + c]);
                af[mi][1] = f2tf32(as[(r0 + 8) * ROWP + ks + c]);
                af[mi][2] = f2tf32(as[r0       * ROWP + ks + c + 4]);
                af[mi][3] = f2tf32(as[(r0 + 8) * ROWP + ks + c + 4]);
            }
#pragma unroll
            for (int ni = 0; ni < 8; ni++) {
                const int r0 = wn * 64 + ni * 8 + g;
                bf[ni][0] = f2tf32(bs[r0 * ROWP + ks + c]);
                bf[ni][1] = f2tf32(bs[r0 * ROWP + ks + c + 4]);
            }
#pragma unroll
            for (int mi = 0; mi < 4; mi++)
#pragma unroll
                for (int ni = 0; ni < 8; ni++)
                    mma_tf32(acc[mi][ni], af[mi][0], af[mi][1], af[mi][2], af[mi][3],
                             bf[ni][0], bf[ni][1]);
        }
    }

    // ---- epilogue -----------------------------------------------------------
#pragma unroll
    for (int mi = 0; mi < 4; mi++) {
#pragma unroll
        for (int ni = 0; ni < 8; ni++) {
#pragma unroll
            for (int r = 0; r < 4; r++) {
                const int m = m0 + wm * 64 + mi * 16 + g + ((r >= 2) ? 8 : 0);
                const int n = n0 + wn * 64 + ni * 8 + 2 * c + (r & 1);
                const float v = acc[mi][ni][r];
                if (MODE == 0) {
                    if (n < 3 * E_) {
                        const int sidx = n / E_;
                        const int l    = n - sidx * E_;
                        const int hh   = l / HS_;
                        const int f    = l - hh * HS_;
                        const int bb   = m / T_;
                        const int t    = m - bb * T_;
                        float* dst = (sidx == 0) ? g_q : ((sidx == 1) ? g_k : g_v);
                        dst[((size_t)(bb * H_ + hh) * T_ + t) * HS_ + f] = v;
                    }
                } else {
                    if (n < E_)
                        out[(size_t)m * E_ + n] = v + bias[n];
                }
            }
        }
    }
}

// ---------------------------------------------------------------------------
// Tensor-core attention v2: one CTA per (b,h), 8 warps in 4 pairs (wm).
// NO CTA-wide barriers after K/V load: each wm pair syncs via named barrier
// (id 1+wm, 64 threads). Column blocks interleaved across wn for balance.
// Q fragments loaded directly from gmem with scale folded in.
// ---------------------------------------------------------------------------
#define TP2 208
#define FP2 80
#define KQ2 84
#define VP  88
#define PP  212

__global__ __launch_bounds__(256, 1)
void attn_mma()
{
    extern __shared__ uint32_t smu[];
    uint32_t* Ks = smu;                  // [208][84]
    uint32_t* Vs = Ks + TP2*KQ2;         // [208][88]
    uint32_t* Pt = Vs + TP2*VP;          // [64][212]
    float* pmax  = (float*)(Pt + 64*PP); // [64][2]
    float* psum  = pmax + 128;           // [64][2]

    const int bh   = blockIdx.x;
    const int tid  = threadIdx.x;
    const int lane = tid & 31;
    const int w    = tid >> 5;
    const int g    = lane >> 2;
    const int c    = lane & 3;
    const int wm   = w & 3;              // pair id; rows wm*16..+15
    const int wn   = w >> 2;             // 0/1 within pair
    const int b    = bh / H_;
    const int h    = bh - b * H_;
    const int barid = 1 + wm;

    const float* qg = g_q + (size_t)bh * T_ * HS_;
    const float* kg = g_k + (size_t)bh * T_ * HS_;
    const float* vg = g_v + (size_t)bh * T_ * HS_;

    // ---- load K, V as tf32 (zero-padded) -----------------------------------
    for (int i = tid; i < TP2*KQ2; i += 256) {
        const int s = i / KQ2, f = i - s * KQ2;
        Ks[i] = (s < T_ && f < HS_) ? f2tf32(kg[s*HS_ + f]) : 0u;
    }
    for (int i = tid; i < TP2*VP; i += 256) {
        const int s = i / VP, f = i - s * VP;
        Vs[i] = (s < T_ && f < HS_) ? f2tf32(vg[s*HS_ + f]) : 0u;
    }
    __syncthreads();   // last CTA-wide barrier

    const float scale = rsqrtf((float)E_);
    const int mr = wm * 16;
    const int rq_lo = mr + g;       // tile-relative row (lo half)
    const int rq_hi = mr + g + 8;

#pragma unroll 1
    for (int t0 = 0; t0 < T_; t0 += 64) {
        const int thi = t0 + mr + 15;

        // ---- S = Q.K^T : A-frags direct from gmem (scaled), interleaved cols
        const int row_lo = (t0 + rq_lo < T_) ? (t0 + rq_lo) : (T_ - 1);
        const int row_hi = (t0 + rq_hi < T_) ? (t0 + rq_hi) : (T_ - 1);

        float acc[13][4];
#pragma unroll
        for (int ni = 0; ni < 13; ni++)
#pragma unroll
            for (int r = 0; r < 4; r++) acc[ni][r] = 0.f;

#pragma unroll 1
        for (int ks = 0; ks < FP2; ks += 8) {
            const int k0 = ks + c, k1 = ks + c + 4;
            const float q00 = (k0 < HS_) ? qg[row_lo*HS_ + k0] : 0.f;
            const float q10 = (k0 < HS_) ? qg[row_hi*HS_ + k0] : 0.f;
            const float q01 = (k1 < HS_) ? qg[row_lo*HS_ + k1] : 0.f;
            const float q11 = (k1 < HS_) ? qg[row_hi*HS_ + k1] : 0.f;
            const uint32_t a0 = f2tf32(q00 * scale);
            const uint32_t a1 = f2tf32(q10 * scale);
            const uint32_t a2 = f2tf32(q01 * scale);
            const uint32_t a3 = f2tf32(q11 * scale);
#pragma unroll
            for (int ni = 0; ni < 13; ni++) {
                const int cb = (2*ni + wn) * 8;          // interleaved block
                if (cb <= thi) {
                    const uint32_t b0 = Ks[(cb+g)*KQ2 + ks + c];
                    const uint32_t b1 = Ks[(cb+g)*KQ2 + ks + c + 4];
                    mma_tf32(acc[ni], a0, a1, a2, a3, b0, b1);
                }
            }
        }

        // ---- softmax (pair-local sync only) --------------------------------
        const int t_lo = t0 + rq_lo;
        const int t_hi = t0 + rq_hi;

        float mlo = -1e30f, mhi = -1e30f;
#pragma unroll
        for (int ni = 0; ni < 13; ni++) {
            const int s0 = (2*ni + wn) * 8 + 2*c;
            const int s1 = s0 + 1;
            if ((s0 <= t_lo) && (s0 < T_) && (t_lo < T_)) mlo = fmaxf(mlo, acc[ni][0]);
            if ((s1 <= t_lo) && (s1 < T_) && (t_lo < T_)) mlo = fmaxf(mlo, acc[ni][1]);
            if ((s0 <= t_hi) && (s0 < T_) && (t_hi < T_)) mhi = fmaxf(mhi, acc[ni][2]);
            if ((s1 <= t_hi) && (s1 < T_) && (t_hi < T_)) mhi = fmaxf(mhi, acc[ni][3]);
        }
#pragma unroll
        for (int off = 1; off <= 2; off <<= 1) {
            mlo = fmaxf(mlo, __shfl_xor_sync(0xffffffffu, mlo, off));
            mhi = fmaxf(mhi, __shfl_xor_sync(0xffffffffu, mhi, off));
        }
        if (c == 0) {
            pmax[rq_lo*2 + wn] = mlo;
            pmax[rq_hi*2 + wn] = mhi;
        }
        named_bar(barid, 64);
        const float gmlo = fmaxf(pmax[rq_lo*2], pmax[rq_lo*2 + 1]);
        const float gmhi = fmaxf(pmax[rq_hi*2], pmax[rq_hi*2 + 1]);

        float slo = 0.f, shi = 0.f;
#pragma unroll
        for (int ni = 0; ni < 13; ni++) {
            const int s0 = (2*ni + wn) * 8 + 2*c;
            const int s1 = s0 + 1;
            const bool ok0l = (s0 <= t_lo) && (s0 < T_) && (t_lo < T_);
            const bool ok1l = (s1 <= t_lo) && (s1 < T_) && (t_lo < T_);
            const bool ok0h = (s0 <= t_hi) && (s0 < T_) && (t_hi < T_);
            const bool ok1h = (s1 <= t_hi) && (s1 < T_) && (t_hi < T_);
            float e0 = ok0l ? __expf(acc[ni][0] - gmlo) : 0.f;
            float e1 = ok1l ? __expf(acc[ni][1] - gmlo) : 0.f;
            float e2 = ok0h ? __expf(acc[ni][2] - gmhi) : 0.f;
            float e3 = ok1h ? __expf(acc[ni][3] - gmhi) : 0.f;
            acc[ni][0] = e0; acc[ni][1] = e1; acc[ni][2] = e2; acc[ni][3] = e3;
            slo += e0 + e1;  shi += e2 + e3;
        }
#pragma unroll
        for (int off = 1; off <= 2; off <<= 1) {
            slo += __shfl_xor_sync(0xffffffffu, slo, off);
            shi += __shfl_xor_sync(0xffffffffu, shi, off);
        }
        if (c == 0) {
            psum[rq_lo*2 + wn] = slo;
            psum[rq_hi*2 + wn] = shi;
        }
        named_bar(barid, 64);
        const float tlo  = psum[rq_lo*2] + psum[rq_lo*2 + 1];
        const float thi2 = psum[rq_hi*2] + psum[rq_hi*2 + 1];
        const float rlo = (tlo  > 0.f) ? (1.f / tlo)  : 0.f;
        const float rhi = (thi2 > 0.f) ? (1.f / thi2) : 0.f;

        // write normalized P (tf32); interleaved cols cover 0..207 over pair
#pragma unroll
        for (int ni = 0; ni < 13; ni++) {
            const int col = (2*ni + wn) * 8 + 2*c;
            uint2 ulo = make_uint2(f2tf32(acc[ni][0]*rlo), f2tf32(acc[ni][1]*rlo));
            uint2 uhi = make_uint2(f2tf32(acc[ni][2]*rhi), f2tf32(acc[ni][3]*rhi));
            *(uint2*)&Pt[rq_lo*PP + col] = ulo;
            *(uint2*)&Pt[rq_hi*PP + col] = uhi;
        }
        named_bar(barid, 64);

        // ---- O = P.V  (warp tile 16 x 40) -----------------------------------
        const int nb2 = wn * 40;
        float o[5][4];
#pragma unroll
        for (int ni = 0; ni < 5; ni++)
#pragma unroll
            for (int r = 0; r < 4; r++) o[ni][r] = 0.f;

        const int kcap   = (thi < T_-1) ? thi : (T_-1);
        const int ks_end = kcap >> 3;
#pragma unroll 1
        for (int ksb = 0; ksb <= ks_end; ksb++) {
            const int ks = ksb * 8;
            const uint32_t a0 = Pt[rq_lo*PP + ks + c];
            const uint32_t a1 = Pt[rq_hi*PP + ks + c];
            const uint32_t a2 = Pt[rq_lo*PP + ks + c + 4];
            const uint32_t a3 = Pt[rq_hi*PP + ks + c + 4];
#pragma unroll
            for (int ni = 0; ni < 5; ni++) {
                const uint32_t b0 = Vs[(ks+c)  *VP + nb2 + ni*8 + g];
                const uint32_t b1 = Vs[(ks+c+4)*VP + nb2 + ni*8 + g];
                mma_tf32(o[ni], a0, a1, a2, a3, b0, b1);
            }
        }

#pragma unroll
        for (int ni = 0; ni < 5; ni++) {
#pragma unroll
            for (int r = 0; r < 4; r++) {
                const int t = t0 + mr + g + ((r >= 2) ? 8 : 0);
                const int f = nb2 + ni*8 + 2*c + (r & 1);
                if (t < T_ && f < HS_)
                    g_att[((size_t)(b*T_ + t))*E_ + h*HS_ + f] = o[ni][r];
            }
        }
        named_bar(barid, 64);   // Pt/pmax/psum safe to reuse next tile
    }
}

// ---------------------------------------------------------------------------
extern "C" void kernel_launch(void* const* d_in, const int* in_sizes, int n_in,
                              void* d_out, int out_size)
{
    const float* x  = (const float*)d_in[0];
    const float* Wq = (const float*)d_in[1];
    const float* Wk = (const float*)d_in[2];
    const float* Wv = (const float*)d_in[3];
    const float* Wo = (const float*)d_in[4];
    const float* bo = (const float*)d_in[5];
    float* out = (float*)d_out;

    cudaFuncSetAttribute(gemm_tf32<0>, cudaFuncAttributeMaxDynamicSharedMemorySize, GEMM_SMEM);
    cudaFuncSetAttribute(gemm_tf32<1>, cudaFuncAttributeMaxDynamicSharedMemorySize, GEMM_SMEM);

    const int att_smem = (TP2*KQ2 + TP2*VP + 64*PP + 256) * (int)sizeof(float);
    cudaFuncSetAttribute(attn_mma, cudaFuncAttributeMaxDynamicSharedMemorySize, att_smem);

    // QKV projection: M=51200 -> 400 tiles of 128, N=1752 -> 14 tiles of 128
    gemm_tf32<0><<<dim3(14, 400), 128, GEMM_SMEM>>>(x, Wq, Wk, Wv, nullptr, nullptr);

    // attention
    attn_mma<<<BH_, 256, att_smem>>>();

    // output projection: N=584 -> 5 tiles
    gemm_tf32<1><<<dim3(5, 400), 128, GEMM_SMEM>>>(nullptr, Wo, nullptr, nullptr, bo, out);
}

// round 9
// speedup vs baseline: 1.0593x; 1.0593x over previous
#include <cuda_runtime.h>
#include <math.h>
#include <stdint.h>

// Problem constants
#define B_  256
#define T_  200
#define E_  584
#define H_  8
#define HS_ 73
#define BH_ (B_*H_)      // 2048
#define M_  (B_*T_)      // 51200

// Scratch (allocation-free rule: __device__ globals)
__device__ float g_q[BH_*T_*HS_];
__device__ float g_k[BH_*T_*HS_];
__device__ float g_v[BH_*T_*HS_];
__device__ float g_att[M_*E_];

__device__ __forceinline__ uint32_t f2tf32(float f) {
    uint32_t r;
    asm("cvt.rna.tf32.f32 %0, %1;" : "=r"(r) : "f"(f));
    return r;
}

__device__ __forceinline__ void mma_tf32(float c[4],
                                         uint32_t a0, uint32_t a1, uint32_t a2, uint32_t a3,
                                         uint32_t b0, uint32_t b1) {
    asm volatile(
        "mma.sync.aligned.m16n8k8.row.col.f32.tf32.tf32.f32 "
        "{%0,%1,%2,%3}, {%4,%5,%6,%7}, {%8,%9}, {%0,%1,%2,%3};"
        : "+f"(c[0]), "+f"(c[1]), "+f"(c[2]), "+f"(c[3])
        : "r"(a0), "r"(a1), "r"(a2), "r"(a3), "r"(b0), "r"(b1));
}

// ldmatrix x4: loads four 8x8 b16 matrices; used to fetch tf32 b32 fragments
// (each 8x8 b32 tile = 8 rows x two 16B halves).
__device__ __forceinline__ void ldm_x4(uint32_t& r0, uint32_t& r1,
                                       uint32_t& r2, uint32_t& r3, uint32_t a) {
    asm volatile("ldmatrix.sync.aligned.m8n8.x4.shared.b16 {%0,%1,%2,%3}, [%4];"
                 : "=r"(r0), "=r"(r1), "=r"(r2), "=r"(r3) : "r"(a));
}

__device__ __forceinline__ uint32_t s2u(const void* p) {
    return (uint32_t)__cvta_generic_to_shared(p);
}
__device__ __forceinline__ void named_bar(int id, int cnt) {
    asm volatile("bar.sync %0, %1;" :: "r"(id), "r"(cnt) : "memory");
}

// ---------------------------------------------------------------------------
// TF32 tensor-core GEMM v5 (ldmatrix fragments):
//   C[m,n] = sum_k A[m,k] * B[n,k]
// CTA 128x128, BK=16, 256 threads (8 warps, 4m x 2n), warp tile 32x64.
// smem holds tf32 (converted at stage time), row-major pitch ROWP=20
// (20 mod 32 => conflict-free ldmatrix half-row addressing).
// ---------------------------------------------------------------------------
#define ROWP 20
#define NSTG 37          // ceil(584/16)
#define TW   (128*ROWP)  // words per tile buffer

template<int MODE>
__global__ __launch_bounds__(256, 2)
void gemm_tf32(const float* __restrict__ Aarg,
               const float* __restrict__ B0,
               const float* __restrict__ B1,
               const float* __restrict__ B2,
               const float* __restrict__ bias,
               float* __restrict__ out)
{
    __shared__ uint32_t As[2][TW];
    __shared__ uint32_t Bs[2][TW];

    const float* A = (MODE == 0) ? Aarg : (const float*)g_att;

    const int tid  = threadIdx.x;
    const int lane = tid & 31;
    const int w    = tid >> 5;
    const int g    = lane >> 2;
    const int c    = lane & 3;
    const int wm   = w & 3;          // 4 m-warps, 32 rows each
    const int wn   = w >> 2;         // 2 n-warps, 64 cols each

    const int m0 = blockIdx.y * 128;
    const int n0 = blockIdx.x * 128;

    float acc[2][8][4];
#pragma unroll
    for (int mi = 0; mi < 2; mi++)
#pragma unroll
        for (int ni = 0; ni < 8; ni++)
#pragma unroll
            for (int r = 0; r < 4; r++) acc[mi][ni][r] = 0.f;

    // staging: thread owns row tid>>1, k-chunks {0,1} (even tid) or {2,3}
    const int row = tid >> 1;
    const int kc0 = (tid & 1) * 2;   // chunk index (4 floats each)

    const float* aptr = A + (size_t)(m0 + row) * E_ + kc0 * 4;

    const float* bptr;
    bool bval;
    {
        int gn = n0 + row;
        if (MODE == 0) {
            bval = gn < 3 * E_;
            int s = gn / E_; if (s > 2) s = 2;
            int l = bval ? gn - s * E_ : 0;
            const float* W = (s == 0) ? B0 : ((s == 1) ? B1 : B2);
            bptr = W + (size_t)l * E_;
        } else {
            bval = gn < E_;
            bptr = B0 + (size_t)(bval ? gn : 0) * E_;
        }
        bptr += kc0 * 4;
    }

    uint32_t* sA = &As[0][row * ROWP + kc0 * 4];
    uint32_t* sB = &Bs[0][row * ROWP + kc0 * 4];

    // ldmatrix lane addressing: rowoff = lane&15, half = lane>>4
    const int lr = lane & 15, lh = lane >> 4;
    uint32_t aAdr[2], bAdr[4];
#pragma unroll
    for (int mi = 0; mi < 2; mi++)
        aAdr[mi] = s2u(&As[0][0]) + (uint32_t)(((wm*32 + mi*16 + lr) * ROWP + lh*4) * 4);
#pragma unroll
    for (int np = 0; np < 4; np++)
        bAdr[np] = s2u(&Bs[0][0]) + (uint32_t)(((wn*64 + np*16 + lr) * ROWP + lh*4) * 4);
    const uint32_t BUFB = TW * 4;

    const float4 z4 = make_float4(0.f, 0.f, 0.f, 0.f);

    // ---- prologue: stage 0 into buffer 0 -----------------------------------
    {
        float4 a0 = *(const float4*)aptr;
        float4 a1 = *(const float4*)(aptr + 4);
        float4 b0 = bval ? *(const float4*)bptr : z4;
        float4 b1 = bval ? *(const float4*)(bptr + 4) : z4;
        *(uint4*)sA       = make_uint4(f2tf32(a0.x), f2tf32(a0.y), f2tf32(a0.z), f2tf32(a0.w));
        *(uint4*)(sA + 4) = make_uint4(f2tf32(a1.x), f2tf32(a1.y), f2tf32(a1.z), f2tf32(a1.w));
        *(uint4*)sB       = make_uint4(f2tf32(b0.x), f2tf32(b0.y), f2tf32(b0.z), f2tf32(b0.w));
        *(uint4*)(sB + 4) = make_uint4(f2tf32(b1.x), f2tf32(b1.y), f2tf32(b1.z), f2tf32(b1.w));
    }
    __syncthreads();

#pragma unroll 1
    for (int s = 0; s < NSTG; s++) {
        const int buf = s & 1;
        const bool more = (s + 1 < NSTG);

        // global loads for next stage
        float4 na0, na1, nb0, nb1;
        if (more) {
            const int k0 = (s + 1) * 16;
            const bool v0 = (k0 + kc0 * 4)     < E_;
            const bool v1 = (k0 + kc0 * 4 + 4) < E_;
            na0 = v0 ? *(const float4*)(aptr + k0)     : z4;
            na1 = v1 ? *(const float4*)(aptr + k0 + 4) : z4;
            nb0 = (v0 && bval) ? *(const float4*)(bptr + k0)     : z4;
            nb1 = (v1 && bval) ? *(const float4*)(bptr + k0 + 4) : z4;
        }

        // compute on current buffer via ldmatrix fragments
        const uint32_t kb = buf * BUFB;
#pragma unroll
        for (int ks = 0; ks < 16; ks += 8) {
            uint32_t a[2][4], bm[4][4];
#pragma unroll
            for (int mi = 0; mi < 2; mi++)
                ldm_x4(a[mi][0], a[mi][1], a[mi][2], a[mi][3],
                       aAdr[mi] + kb + ks * 4);
#pragma unroll
            for (int np = 0; np < 4; np++)
                ldm_x4(bm[np][0], bm[np][1], bm[np][2], bm[np][3],
                       bAdr[np] + kb + ks * 4);
#pragma unroll
            for (int mi = 0; mi < 2; mi++)
#pragma unroll
                for (int np = 0; np < 4; np++) {
                    mma_tf32(acc[mi][2*np],   a[mi][0], a[mi][1], a[mi][2], a[mi][3],
                             bm[np][0], bm[np][2]);
                    mma_tf32(acc[mi][2*np+1], a[mi][0], a[mi][1], a[mi][2], a[mi][3],
                             bm[np][1], bm[np][3]);
                }
        }

        // stage next buffer
        if (more) {
            uint32_t* dA = sA + (buf ^ 1) * TW;
            uint32_t* dB = sB + (buf ^ 1) * TW;
            dA[0] = f2tf32(na0.x); dA[1] = f2tf32(na0.y); dA[2] = f2tf32(na0.z); dA[3] = f2tf32(na0.w);
            dA[4] = f2tf32(na1.x); dA[5] = f2tf32(na1.y); dA[6] = f2tf32(na1.z); dA[7] = f2tf32(na1.w);
            dB[0] = f2tf32(nb0.x); dB[1] = f2tf32(nb0.y); dB[2] = f2tf32(nb0.z); dB[3] = f2tf32(nb0.w);
            dB[4] = f2tf32(nb1.x); dB[5] = f2tf32(nb1.y); dB[6] = f2tf32(nb1.z); dB[7] = f2tf32(nb1.w);
        }
        __syncthreads();
    }

    // ---- epilogue -----------------------------------------------------------
#pragma unroll
    for (int mi = 0; mi < 2; mi++) {
#pragma unroll
        for (int ni = 0; ni < 8; ni++) {
#pragma unroll
            for (int r = 0; r < 4; r++) {
                const int m = m0 + wm * 32 + mi * 16 + g + ((r >= 2) ? 8 : 0);
                const int n = n0 + wn * 64 + ni * 8 + 2 * c + (r & 1);
                const float v = acc[mi][ni][r];
                if (MODE == 0) {
                    if (n < 3 * E_) {
                        const int sidx = n / E_;
                        const int l    = n - sidx * E_;
                        const int hh   = l / HS_;
                        const int f    = l - hh * HS_;
                        const int bb   = m / T_;
                        const int t    = m - bb * T_;
                        float* dst = (sidx == 0) ? g_q : ((sidx == 1) ? g_k : g_v);
                        dst[((size_t)(bb * H_ + hh) * T_ + t) * HS_ + f] = v;
                    }
                } else {
                    if (n < E_)
                        out[(size_t)m * E_ + n] = v + bias[n];
                }
            }
        }
    }
}

// ---------------------------------------------------------------------------
// Tensor-core attention v3: pair-local barriers, ldmatrix K/P fragments,
// 16-col chunks interleaved across wn for causal balance.
// ---------------------------------------------------------------------------
#define TP2 208
#define FP2 80
#define KQ2 84
#define VP  88
#define PP  212

__global__ __launch_bounds__(256, 1)
void attn_mma()
{
    extern __shared__ uint32_t smu[];
    uint32_t* Ks = smu;                  // [208][84]  tf32, n-major
    uint32_t* Vs = Ks + TP2*KQ2;         // [208][88]  tf32, k-major
    uint32_t* Pt = Vs + TP2*VP;          // [64][212]  tf32
    float* pmax  = (float*)(Pt + 64*PP); // [64][2]
    float* psum  = pmax + 128;           // [64][2]

    const int bh   = blockIdx.x;
    const int tid  = threadIdx.x;
    const int lane = tid & 31;
    const int w    = tid >> 5;
    const int g    = lane >> 2;
    const int c    = lane & 3;
    const int wm   = w & 3;              // pair id; rows wm*16..+15
    const int wn   = w >> 2;             // 0/1 within pair
    const int b    = bh / H_;
    const int h    = bh - b * H_;
    const int barid = 1 + wm;

    const float* qg = g_q + (size_t)bh * T_ * HS_;
    const float* kg = g_k + (size_t)bh * T_ * HS_;
    const float* vg = g_v + (size_t)bh * T_ * HS_;

    // ---- load K, V as tf32 (zero-padded) -----------------------------------
    for (int i = tid; i < TP2*KQ2; i += 256) {
        const int s = i / KQ2, f = i - s * KQ2;
        Ks[i] = (s < T_ && f < HS_) ? f2tf32(kg[s*HS_ + f]) : 0u;
    }
    for (int i = tid; i < TP2*VP; i += 256) {
        const int s = i / VP, f = i - s * VP;
        Vs[i] = (s < T_ && f < HS_) ? f2tf32(vg[s*HS_ + f]) : 0u;
    }
    __syncthreads();   // only CTA-wide barrier

    const float scale = rsqrtf((float)E_);
    const int mr = wm * 16;
    const int rq_lo = mr + g;
    const int rq_hi = mr + g + 8;

    const int lr = lane & 15, lh = lane >> 4;
    const uint32_t kBase = s2u(Ks) + (uint32_t)((lr * KQ2 + lh * 4) * 4);
    const uint32_t pBase = s2u(Pt) + (uint32_t)(((mr + lr) * PP + lh * 4) * 4);

#pragma unroll 1
    for (int t0 = 0; t0 < T_; t0 += 64) {
        const int thi = t0 + mr + 15;

        const int row_lo = (t0 + rq_lo < T_) ? (t0 + rq_lo) : (T_ - 1);
        const int row_hi = (t0 + rq_hi < T_) ? (t0 + rq_hi) : (T_ - 1);

        float acc[7][2][4];
#pragma unroll
        for (int u = 0; u < 7; u++)
#pragma unroll
            for (int e = 0; e < 2; e++)
#pragma unroll
                for (int r = 0; r < 4; r++) acc[u][e][r] = 0.f;

        // ---- S = Q.K^T : Q frags from gmem (scaled), K frags via ldmatrix --
#pragma unroll 1
        for (int ks = 0; ks < FP2; ks += 8) {
            const int k0 = ks + c, k1 = ks + c + 4;
            const float q00 = (k0 < HS_) ? qg[row_lo*HS_ + k0] : 0.f;
            const float q10 = (k0 < HS_) ? qg[row_hi*HS_ + k0] : 0.f;
            const float q01 = (k1 < HS_) ? qg[row_lo*HS_ + k1] : 0.f;
            const float q11 = (k1 < HS_) ? qg[row_hi*HS_ + k1] : 0.f;
            const uint32_t a0 = f2tf32(q00 * scale);
            const uint32_t a1 = f2tf32(q10 * scale);
            const uint32_t a2 = f2tf32(q01 * scale);
            const uint32_t a3 = f2tf32(q11 * scale);
#pragma unroll
            for (int u = 0; u < 7; u++) {
                const int chunk = 2*u + wn;
                const int cb = chunk * 16;
                if (chunk < 13 && cb <= thi) {
                    uint32_t b0, b1, b2, b3;
                    ldm_x4(b0, b1, b2, b3, kBase + (uint32_t)((cb * KQ2 + ks) * 4));
                    mma_tf32(acc[u][0], a0, a1, a2, a3, b0, b2);
                    mma_tf32(acc[u][1], a0, a1, a2, a3, b1, b3);
                }
            }
        }

        // ---- softmax (pair-local sync only) --------------------------------
        const int t_lo = t0 + rq_lo;
        const int t_hi = t0 + rq_hi;

        float mlo = -1e30f, mhi = -1e30f;
#pragma unroll
        for (int u = 0; u < 7; u++)
#pragma unroll
            for (int e = 0; e < 2; e++) {
                const int s0 = (2*u + wn)*16 + e*8 + 2*c;
                const int s1 = s0 + 1;
                if ((s0 <= t_lo) && (s0 < T_) && (t_lo < T_)) mlo = fmaxf(mlo, acc[u][e][0]);
                if ((s1 <= t_lo) && (s1 < T_) && (t_lo < T_)) mlo = fmaxf(mlo, acc[u][e][1]);
                if ((s0 <= t_hi) && (s0 < T_) && (t_hi < T_)) mhi = fmaxf(mhi, acc[u][e][2]);
                if ((s1 <= t_hi) && (s1 < T_) && (t_hi < T_)) mhi = fmaxf(mhi, acc[u][e][3]);
            }
#pragma unroll
        for (int off = 1; off <= 2; off <<= 1) {
            mlo = fmaxf(mlo, __shfl_xor_sync(0xffffffffu, mlo, off));
            mhi = fmaxf(mhi, __shfl_xor_sync(0xffffffffu, mhi, off));
        }
        if (c == 0) {
            pmax[rq_lo*2 + wn] = mlo;
            pmax[rq_hi*2 + wn] = mhi;
        }
        named_bar(barid, 64);
        const float gmlo = fmaxf(pmax[rq_lo*2], pmax[rq_lo*2 + 1]);
        const float gmhi = fmaxf(pmax[rq_hi*2], pmax[rq_hi*2 + 1]);

        float slo = 0.f, shi = 0.f;
#pragma unroll
        for (int u = 0; u < 7; u++)
#pragma unroll
            for (int e = 0; e < 2; e++) {
                const int s0 = (2*u + wn)*16 + e*8 + 2*c;
                const int s1 = s0 + 1;
                const bool ok0l = (s0 <= t_lo) && (s0 < T_) && (t_lo < T_);
                const bool ok1l = (s1 <= t_lo) && (s1 < T_) && (t_lo < T_);
                const bool ok0h = (s0 <= t_hi) && (s0 < T_) && (t_hi < T_);
                const bool ok1h = (s1 <= t_hi) && (s1 < T_) && (t_hi < T_);
                float e0 = ok0l ? __expf(acc[u][e][0] - gmlo) : 0.f;
                float e1 = ok1l ? __expf(acc[u][e][1] - gmlo) : 0.f;
                float e2 = ok0h ? __expf(acc[u][e][2] - gmhi) : 0.f;
                float e3 = ok1h ? __expf(acc[u][e][3] - gmhi) : 0.f;
                acc[u][e][0] = e0; acc[u][e][1] = e1;
                acc[u][e][2] = e2; acc[u][e][3] = e3;
                slo += e0 + e1;  shi += e2 + e3;
            }
#pragma unroll
        for (int off = 1; off <= 2; off <<= 1) {
            slo += __shfl_xor_sync(0xffffffffu, slo, off);
            shi += __shfl_xor_sync(0xffffffffu, shi, off);
        }
        if (c == 0) {
            psum[rq_lo*2 + wn] = slo;
            psum[rq_hi*2 + wn] = shi;
        }
        named_bar(barid, 64);
        const float tlo  = psum[rq_lo*2] + psum[rq_lo*2 + 1];
        const float thi2 = psum[rq_hi*2] + psum[rq_hi*2 + 1];
        const float rlo = (tlo  > 0.f) ? (1.f / tlo)  : 0.f;
        const float rhi = (thi2 > 0.f) ? (1.f / thi2) : 0.f;

        // write normalized P (tf32)
#pragma unroll
        for (int u = 0; u < 7; u++) {
            const int chunk = 2*u + wn;
            if (chunk < 13) {
#pragma unroll
                for (int e = 0; e < 2; e++) {
                    const int col = chunk*16 + e*8 + 2*c;
                    uint2 ulo = make_uint2(f2tf32(acc[u][e][0]*rlo), f2tf32(acc[u][e][1]*rlo));
                    uint2 uhi = make_uint2(f2tf32(acc[u][e][2]*rhi), f2tf32(acc[u][e][3]*rhi));
                    *(uint2*)&Pt[rq_lo*PP + col] = ulo;
                    *(uint2*)&Pt[rq_hi*PP + col] = uhi;
                }
            }
        }
        named_bar(barid, 64);

        // ---- O = P.V  (warp tile 16 x 40), P frags via ldmatrix -------------
        const int nb2 = wn * 40;
        float o[5][4];
#pragma unroll
        for (int ni = 0; ni < 5; ni++)
#pragma unroll
            for (int r = 0; r < 4; r++) o[ni][r] = 0.f;

        const int kcap   = (thi < T_-1) ? thi : (T_-1);
        const int ks_end = kcap >> 3;
#pragma unroll 1
        for (int ksb = 0; ksb <= ks_end; ksb++) {
            const int ks = ksb * 8;
            uint32_t a0, a1, a2, a3;
            ldm_x4(a0, a1, a2, a3, pBase + (uint32_t)(ks * 4));
#pragma unroll
            for (int ni = 0; ni < 5; ni++) {
                const uint32_t b0 = Vs[(ks+c)  *VP + nb2 + ni*8 + g];
                const uint32_t b1 = Vs[(ks+c+4)*VP + nb2 + ni*8 + g];
                mma_tf32(o[ni], a0, a1, a2, a3, b0, b1);
            }
        }

#pragma unroll
        for (int ni = 0; ni < 5; ni++) {
#pragma unroll
            for (int r = 0; r < 4; r++) {
                const int t = t0 + mr + g + ((r >= 2) ? 8 : 0);
                const int f = nb2 + ni*8 + 2*c + (r & 1);
                if (t < T_ && f < HS_)
                    g_att[((size_t)(b*T_ + t))*E_ + h*HS_ + f] = o[ni][r];
            }
        }
        named_bar(barid, 64);   // Pt/pmax/psum safe to reuse next tile
    }
}

// ---------------------------------------------------------------------------
extern "C" void kernel_launch(void* const* d_in, const int* in_sizes, int n_in,
                              void* d_out, int out_size)
{
    const float* x  = (const float*)d_in[0];
    const float* Wq = (const float*)d_in[1];
    const float* Wk = (const float*)d_in[2];
    const float* Wv = (const float*)d_in[3];
    const float* Wo = (const float*)d_in[4];
    const float* bo = (const float*)d_in[5];
    float* out = (float*)d_out;

    const int att_smem = (TP2*KQ2 + TP2*VP + 64*PP + 256) * (int)sizeof(float);
    cudaFuncSetAttribute(attn_mma, cudaFuncAttributeMaxDynamicSharedMemorySize, att_smem);

    // QKV projection: M=51200 -> 400 tiles of 128, N=1752 -> 14 tiles of 128
    gemm_tf32<0><<<dim3(14, 400), 256>>>(x, Wq, Wk, Wv, nullptr, nullptr);

    // attention
    attn_mma<<<BH_, 256, att_smem>>>();

    // output projection: N=584 -> 5 tiles
    gemm_tf32<1><<<dim3(5, 400), 256>>>(nullptr, Wo, nullptr, nullptr, bo, out);
}

// round 10
// speedup vs baseline: 1.1358x; 1.0721x over previous
#include <cuda_runtime.h>
#include <math.h>
#include <stdint.h>

// Problem constants
#define B_  256
#define T_  200
#define E_  584
#define H_  8
#define HS_ 73
#define BH_ (B_*H_)      // 2048
#define M_  (B_*T_)      // 51200

// Scratch (allocation-free rule: __device__ globals)
__device__ float g_q[BH_*T_*HS_];
__device__ float g_k[BH_*T_*HS_];
__device__ float g_v[BH_*T_*HS_];
__device__ float g_att[M_*E_];

__device__ __forceinline__ uint32_t f2tf32(float f) {
    uint32_t r;
    asm("cvt.rna.tf32.f32 %0, %1;" : "=r"(r) : "f"(f));
    return r;
}

__device__ __forceinline__ void mma_tf32(float c[4],
                                         uint32_t a0, uint32_t a1, uint32_t a2, uint32_t a3,
                                         uint32_t b0, uint32_t b1) {
    asm volatile(
        "mma.sync.aligned.m16n8k8.row.col.f32.tf32.tf32.f32 "
        "{%0,%1,%2,%3}, {%4,%5,%6,%7}, {%8,%9}, {%0,%1,%2,%3};"
        : "+f"(c[0]), "+f"(c[1]), "+f"(c[2]), "+f"(c[3])
        : "r"(a0), "r"(a1), "r"(a2), "r"(a3), "r"(b0), "r"(b1));
}

// ldmatrix x4: four 8x8 b16 tiles == one tf32 16x8 fragment (two 16B halves/row)
__device__ __forceinline__ void ldm_x4(uint32_t& r0, uint32_t& r1,
                                       uint32_t& r2, uint32_t& r3, uint32_t a) {
    asm volatile("ldmatrix.sync.aligned.m8n8.x4.shared.b16 {%0,%1,%2,%3}, [%4];"
                 : "=r"(r0), "=r"(r1), "=r"(r2), "=r"(r3) : "r"(a));
}

__device__ __forceinline__ uint32_t s2u(const void* p) {
    return (uint32_t)__cvta_generic_to_shared(p);
}
__device__ __forceinline__ void named_bar(int id, int cnt) {
    asm volatile("bar.sync %0, %1;" :: "r"(id), "r"(cnt) : "memory");
}

// ---------------------------------------------------------------------------
// TF32 tensor-core GEMM (R9, unchanged): C[m,n] = sum_k A[m,k] * B[n,k]
// CTA 128x128, BK=16, 256 threads, warp tile 32x64, ldmatrix fragments.
// ---------------------------------------------------------------------------
#define ROWP 20
#define NSTG 37
#define TW   (128*ROWP)

template<int MODE>
__global__ __launch_bounds__(256, 2)
void gemm_tf32(const float* __restrict__ Aarg,
               const float* __restrict__ B0,
               const float* __restrict__ B1,
               const float* __restrict__ B2,
               const float* __restrict__ bias,
               float* __restrict__ out)
{
    __shared__ uint32_t As[2][TW];
    __shared__ uint32_t Bs[2][TW];

    const float* A = (MODE == 0) ? Aarg : (const float*)g_att;

    const int tid  = threadIdx.x;
    const int lane = tid & 31;
    const int w    = tid >> 5;
    const int g    = lane >> 2;
    const int c    = lane & 3;
    const int wm   = w & 3;
    const int wn   = w >> 2;

    const int m0 = blockIdx.y * 128;
    const int n0 = blockIdx.x * 128;

    float acc[2][8][4];
#pragma unroll
    for (int mi = 0; mi < 2; mi++)
#pragma unroll
        for (int ni = 0; ni < 8; ni++)
#pragma unroll
            for (int r = 0; r < 4; r++) acc[mi][ni][r] = 0.f;

    const int row = tid >> 1;
    const int kc0 = (tid & 1) * 2;

    const float* aptr = A + (size_t)(m0 + row) * E_ + kc0 * 4;

    const float* bptr;
    bool bval;
    {
        int gn = n0 + row;
        if (MODE == 0) {
            bval = gn < 3 * E_;
            int s = gn / E_; if (s > 2) s = 2;
            int l = bval ? gn - s * E_ : 0;
            const float* W = (s == 0) ? B0 : ((s == 1) ? B1 : B2);
            bptr = W + (size_t)l * E_;
        } else {
            bval = gn < E_;
            bptr = B0 + (size_t)(bval ? gn : 0) * E_;
        }
        bptr += kc0 * 4;
    }

    uint32_t* sA = &As[0][row * ROWP + kc0 * 4];
    uint32_t* sB = &Bs[0][row * ROWP + kc0 * 4];

    const int lr = lane & 15, lh = lane >> 4;
    uint32_t aAdr[2], bAdr[4];
#pragma unroll
    for (int mi = 0; mi < 2; mi++)
        aAdr[mi] = s2u(&As[0][0]) + (uint32_t)(((wm*32 + mi*16 + lr) * ROWP + lh*4) * 4);
#pragma unroll
    for (int np = 0; np < 4; np++)
        bAdr[np] = s2u(&Bs[0][0]) + (uint32_t)(((wn*64 + np*16 + lr) * ROWP + lh*4) * 4);
    const uint32_t BUFB = TW * 4;

    const float4 z4 = make_float4(0.f, 0.f, 0.f, 0.f);

    {
        float4 a0 = *(const float4*)aptr;
        float4 a1 = *(const float4*)(aptr + 4);
        float4 b0 = bval ? *(const float4*)bptr : z4;
        float4 b1 = bval ? *(const float4*)(bptr + 4) : z4;
        *(uint4*)sA       = make_uint4(f2tf32(a0.x), f2tf32(a0.y), f2tf32(a0.z), f2tf32(a0.w));
        *(uint4*)(sA + 4) = make_uint4(f2tf32(a1.x), f2tf32(a1.y), f2tf32(a1.z), f2tf32(a1.w));
        *(uint4*)sB       = make_uint4(f2tf32(b0.x), f2tf32(b0.y), f2tf32(b0.z), f2tf32(b0.w));
        *(uint4*)(sB + 4) = make_uint4(f2tf32(b1.x), f2tf32(b1.y), f2tf32(b1.z), f2tf32(b1.w));
    }
    __syncthreads();

#pragma unroll 1
    for (int s = 0; s < NSTG; s++) {
        const int buf = s & 1;
        const bool more = (s + 1 < NSTG);

        float4 na0, na1, nb0, nb1;
        if (more) {
            const int k0 = (s + 1) * 16;
            const bool v0 = (k0 + kc0 * 4)     < E_;
            const bool v1 = (k0 + kc0 * 4 + 4) < E_;
            na0 = v0 ? *(const float4*)(aptr + k0)     : z4;
            na1 = v1 ? *(const float4*)(aptr + k0 + 4) : z4;
            nb0 = (v0 && bval) ? *(const float4*)(bptr + k0)     : z4;
            nb1 = (v1 && bval) ? *(const float4*)(bptr + k0 + 4) : z4;
        }

        const uint32_t kb = buf * BUFB;
#pragma unroll
        for (int ks = 0; ks < 16; ks += 8) {
            uint32_t a[2][4], bm[4][4];
#pragma unroll
            for (int mi = 0; mi < 2; mi++)
                ldm_x4(a[mi][0], a[mi][1], a[mi][2], a[mi][3],
                       aAdr[mi] + kb + ks * 4);
#pragma unroll
            for (int np = 0; np < 4; np++)
                ldm_x4(bm[np][0], bm[np][1], bm[np][2], bm[np][3],
                       bAdr[np] + kb + ks * 4);
#pragma unroll
            for (int mi = 0; mi < 2; mi++)
#pragma unroll
                for (int np = 0; np < 4; np++) {
                    mma_tf32(acc[mi][2*np],   a[mi][0], a[mi][1], a[mi][2], a[mi][3],
                             bm[np][0], bm[np][2]);
                    mma_tf32(acc[mi][2*np+1], a[mi][0], a[mi][1], a[mi][2], a[mi][3],
                             bm[np][1], bm[np][3]);
                }
        }

        if (more) {
            uint32_t* dA = sA + (buf ^ 1) * TW;
            uint32_t* dB = sB + (buf ^ 1) * TW;
            dA[0] = f2tf32(na0.x); dA[1] = f2tf32(na0.y); dA[2] = f2tf32(na0.z); dA[3] = f2tf32(na0.w);
            dA[4] = f2tf32(na1.x); dA[5] = f2tf32(na1.y); dA[6] = f2tf32(na1.z); dA[7] = f2tf32(na1.w);
            dB[0] = f2tf32(nb0.x); dB[1] = f2tf32(nb0.y); dB[2] = f2tf32(nb0.z); dB[3] = f2tf32(nb0.w);
            dB[4] = f2tf32(nb1.x); dB[5] = f2tf32(nb1.y); dB[6] = f2tf32(nb1.z); dB[7] = f2tf32(nb1.w);
        }
        __syncthreads();
    }

#pragma unroll
    for (int mi = 0; mi < 2; mi++) {
#pragma unroll
        for (int ni = 0; ni < 8; ni++) {
#pragma unroll
            for (int r = 0; r < 4; r++) {
                const int m = m0 + wm * 32 + mi * 16 + g + ((r >= 2) ? 8 : 0);
                const int n = n0 + wn * 64 + ni * 8 + 2 * c + (r & 1);
                const float v = acc[mi][ni][r];
                if (MODE == 0) {
                    if (n < 3 * E_) {
                        const int sidx = n / E_;
                        const int l    = n - sidx * E_;
                        const int hh   = l / HS_;
                        const int f    = l - hh * HS_;
                        const int bb   = m / T_;
                        const int t    = m - bb * T_;
                        float* dst = (sidx == 0) ? g_q : ((sidx == 1) ? g_k : g_v);
                        dst[((size_t)(bb * H_ + hh) * T_ + t) * HS_ + f] = v;
                    }
                } else {
                    if (n < E_)
                        out[(size_t)m * E_ + n] = v + bias[n];
                }
            }
        }
    }
}

// ---------------------------------------------------------------------------
// Tensor-core attention v4: 512 threads (16 warps) per (b,h) CTA.
// 4 teams (wm) x 4 warps (wn). Team owns 16 rows per 64-row Q tile.
// Score cols: 16-col chunks interleaved mod 4 across wn (causal balance).
// PV: f-tiles (8 cols) interleaved mod 4 across wn.
// Team-local named barriers (128 threads) only.
// ---------------------------------------------------------------------------
#define TP2 208
#define FP2 80
#define KQ2 84
#define VP  88
#define PP  212

__global__ __launch_bounds__(512, 1)
void attn_mma()
{
    extern __shared__ uint32_t smu[];
    uint32_t* Ks = smu;                  // [208][84]  tf32, n-major
    uint32_t* Vs = Ks + TP2*KQ2;         // [208][88]  tf32, k-major
    uint32_t* Pt = Vs + TP2*VP;          // [64][212]  tf32
    float* pmax  = (float*)(Pt + 64*PP); // [64][4]
    float* psum  = pmax + 256;           // [64][4]

    const int bh   = blockIdx.x;
    const int tid  = threadIdx.x;
    const int lane = tid & 31;
    const int w    = tid >> 5;           // 0..15
    const int g    = lane >> 2;
    const int c    = lane & 3;
    const int wm   = w & 3;              // team id; rows wm*16..+15
    const int wn   = w >> 2;             // 0..3 within team
    const int b    = bh / H_;
    const int h    = bh - b * H_;
    const int barid = 1 + wm;

    const float* qg = g_q + (size_t)bh * T_ * HS_;
    const float* kg = g_k + (size_t)bh * T_ * HS_;
    const float* vg = g_v + (size_t)bh * T_ * HS_;

    // ---- load K, V as tf32 (zero-padded) -----------------------------------
    for (int i = tid; i < TP2*KQ2; i += 512) {
        const int s = i / KQ2, f = i - s * KQ2;
        Ks[i] = (s < T_ && f < HS_) ? f2tf32(kg[s*HS_ + f]) : 0u;
    }
    for (int i = tid; i < TP2*VP; i += 512) {
        const int s = i / VP, f = i - s * VP;
        Vs[i] = (s < T_ && f < HS_) ? f2tf32(vg[s*HS_ + f]) : 0u;
    }
    __syncthreads();   // only CTA-wide barrier

    const float scale = rsqrtf((float)E_);
    const int mr = wm * 16;
    const int rq_lo = mr + g;
    const int rq_hi = mr + g + 8;

    const int lr = lane & 15, lh = lane >> 4;
    const uint32_t kBase = s2u(Ks) + (uint32_t)((lr * KQ2 + lh * 4) * 4);
    const uint32_t pBase = s2u(Pt) + (uint32_t)(((mr + lr) * PP + lh * 4) * 4);

#pragma unroll 1
    for (int t0 = 0; t0 < T_; t0 += 64) {
        const int thi = t0 + mr + 15;

        const int row_lo = (t0 + rq_lo < T_) ? (t0 + rq_lo) : (T_ - 1);
        const int row_hi = (t0 + rq_hi < T_) ? (t0 + rq_hi) : (T_ - 1);

        // acc[u]: 16-col chunk (4u+wn); [2] = 8-col half; [4] = mma C frag
        float acc[4][2][4];
#pragma unroll
        for (int u = 0; u < 4; u++)
#pragma unroll
            for (int e = 0; e < 2; e++)
#pragma unroll
                for (int r = 0; r < 4; r++) acc[u][e][r] = 0.f;

        // ---- S = Q.K^T : Q frags from gmem (scaled), K frags via ldmatrix --
#pragma unroll 1
        for (int ks = 0; ks < FP2; ks += 8) {
            const int k0 = ks + c, k1 = ks + c + 4;
            const float q00 = (k0 < HS_) ? qg[row_lo*HS_ + k0] : 0.f;
            const float q10 = (k0 < HS_) ? qg[row_hi*HS_ + k0] : 0.f;
            const float q01 = (k1 < HS_) ? qg[row_lo*HS_ + k1] : 0.f;
            const float q11 = (k1 < HS_) ? qg[row_hi*HS_ + k1] : 0.f;
            const uint32_t a0 = f2tf32(q00 * scale);
            const uint32_t a1 = f2tf32(q10 * scale);
            const uint32_t a2 = f2tf32(q01 * scale);
            const uint32_t a3 = f2tf32(q11 * scale);
#pragma unroll
            for (int u = 0; u < 4; u++) {
                const int chunk = 4*u + wn;
                const int cb = chunk * 16;
                if (chunk < 13 && cb <= thi) {
                    uint32_t b0, b1, b2, b3;
                    ldm_x4(b0, b1, b2, b3, kBase + (uint32_t)((cb * KQ2 + ks) * 4));
                    mma_tf32(acc[u][0], a0, a1, a2, a3, b0, b2);
                    mma_tf32(acc[u][1], a0, a1, a2, a3, b1, b3);
                }
            }
        }

        // ---- softmax (team-local sync) --------------------------------------
        const int t_lo = t0 + rq_lo;
        const int t_hi = t0 + rq_hi;

        float mlo = -1e30f, mhi = -1e30f;
#pragma unroll
        for (int u = 0; u < 4; u++)
#pragma unroll
            for (int e = 0; e < 2; e++) {
                const int s0 = (4*u + wn)*16 + e*8 + 2*c;
                const int s1 = s0 + 1;
                if ((s0 <= t_lo) && (s0 < T_) && (t_lo < T_)) mlo = fmaxf(mlo, acc[u][e][0]);
                if ((s1 <= t_lo) && (s1 < T_) && (t_lo < T_)) mlo = fmaxf(mlo, acc[u][e][1]);
                if ((s0 <= t_hi) && (s0 < T_) && (t_hi < T_)) mhi = fmaxf(mhi, acc[u][e][2]);
                if ((s1 <= t_hi) && (s1 < T_) && (t_hi < T_)) mhi = fmaxf(mhi, acc[u][e][3]);
            }
#pragma unroll
        for (int off = 1; off <= 2; off <<= 1) {
            mlo = fmaxf(mlo, __shfl_xor_sync(0xffffffffu, mlo, off));
            mhi = fmaxf(mhi, __shfl_xor_sync(0xffffffffu, mhi, off));
        }
        if (c == 0) {
            pmax[rq_lo*4 + wn] = mlo;
            pmax[rq_hi*4 + wn] = mhi;
        }
        named_bar(barid, 128);
        const float gmlo = fmaxf(fmaxf(pmax[rq_lo*4], pmax[rq_lo*4+1]),
                                 fmaxf(pmax[rq_lo*4+2], pmax[rq_lo*4+3]));
        const float gmhi = fmaxf(fmaxf(pmax[rq_hi*4], pmax[rq_hi*4+1]),
                                 fmaxf(pmax[rq_hi*4+2], pmax[rq_hi*4+3]));

        float slo = 0.f, shi = 0.f;
#pragma unroll
        for (int u = 0; u < 4; u++)
#pragma unroll
            for (int e = 0; e < 2; e++) {
                const int s0 = (4*u + wn)*16 + e*8 + 2*c;
                const int s1 = s0 + 1;
                const bool ok0l = (s0 <= t_lo) && (s0 < T_) && (t_lo < T_);
                const bool ok1l = (s1 <= t_lo) && (s1 < T_) && (t_lo < T_);
                const bool ok0h = (s0 <= t_hi) && (s0 < T_) && (t_hi < T_);
                const bool ok1h = (s1 <= t_hi) && (s1 < T_) && (t_hi < T_);
                float e0 = ok0l ? __expf(acc[u][e][0] - gmlo) : 0.f;
                float e1 = ok1l ? __expf(acc[u][e][1] - gmlo) : 0.f;
                float e2 = ok0h ? __expf(acc[u][e][2] - gmhi) : 0.f;
                float e3 = ok1h ? __expf(acc[u][e][3] - gmhi) : 0.f;
                acc[u][e][0] = e0; acc[u][e][1] = e1;
                acc[u][e][2] = e2; acc[u][e][3] = e3;
                slo += e0 + e1;  shi += e2 + e3;
            }
#pragma unroll
        for (int off = 1; off <= 2; off <<= 1) {
            slo += __shfl_xor_sync(0xffffffffu, slo, off);
            shi += __shfl_xor_sync(0xffffffffu, shi, off);
        }
        if (c == 0) {
            psum[rq_lo*4 + wn] = slo;
            psum[rq_hi*4 + wn] = shi;
        }
        named_bar(barid, 128);
        const float tlo  = psum[rq_lo*4] + psum[rq_lo*4+1] + psum[rq_lo*4+2] + psum[rq_lo*4+3];
        const float thi2 = psum[rq_hi*4] + psum[rq_hi*4+1] + psum[rq_hi*4+2] + psum[rq_hi*4+3];
        const float rlo = (tlo  > 0.f) ? (1.f / tlo)  : 0.f;
        const float rhi = (thi2 > 0.f) ? (1.f / thi2) : 0.f;

        // write normalized P (tf32)
#pragma unroll
        for (int u = 0; u < 4; u++) {
            const int chunk = 4*u + wn;
            if (chunk < 13) {
#pragma unroll
                for (int e = 0; e < 2; e++) {
                    const int col = chunk*16 + e*8 + 2*c;
                    uint2 ulo = make_uint2(f2tf32(acc[u][e][0]*rlo), f2tf32(acc[u][e][1]*rlo));
                    uint2 uhi = make_uint2(f2tf32(acc[u][e][2]*rhi), f2tf32(acc[u][e][3]*rhi));
                    *(uint2*)&Pt[rq_lo*PP + col] = ulo;
                    *(uint2*)&Pt[rq_hi*PP + col] = uhi;
                }
            }
        }
        named_bar(barid, 128);

        // ---- O = P.V : f-tiles nt = wn + 4j (10 tiles of 8 cols) ------------
        float o[3][4];
#pragma unroll
        for (int j = 0; j < 3; j++)
#pragma unroll
            for (int r = 0; r < 4; r++) o[j][r] = 0.f;

        const int kcap   = (thi < T_-1) ? thi : (T_-1);
        const int ks_end = kcap >> 3;
#pragma unroll 1
        for (int ksb = 0; ksb <= ks_end; ksb++) {
            const int ks = ksb * 8;
            uint32_t a0, a1, a2, a3;
            ldm_x4(a0, a1, a2, a3, pBase + (uint32_t)(ks * 4));
#pragma unroll
            for (int j = 0; j < 3; j++) {
                const int nt = wn + 4*j;
                if (nt < 10) {
                    const uint32_t b0 = Vs[(ks+c)  *VP + nt*8 + g];
                    const uint32_t b1 = Vs[(ks+c+4)*VP + nt*8 + g];
                    mma_tf32(o[j], a0, a1, a2, a3, b0, b1);
                }
            }
        }

#pragma unroll
        for (int j = 0; j < 3; j++) {
            const int nt = wn + 4*j;
            if (nt < 10) {
#pragma unroll
                for (int r = 0; r < 4; r++) {
                    const int t = t0 + mr + g + ((r >= 2) ? 8 : 0);
                    const int f = nt*8 + 2*c + (r & 1);
                    if (t < T_ && f < HS_)
                        g_att[((size_t)(b*T_ + t))*E_ + h*HS_ + f] = o[j][r];
                }
            }
        }
        named_bar(barid, 128);   // Pt/pmax/psum safe to reuse next tile
    }
}

// ---------------------------------------------------------------------------
extern "C" void kernel_launch(void* const* d_in, const int* in_sizes, int n_in,
                              void* d_out, int out_size)
{
    const float* x  = (const float*)d_in[0];
    const float* Wq = (const float*)d_in[1];
    const float* Wk = (const float*)d_in[2];
    const float* Wv = (const float*)d_in[3];
    const float* Wo = (const float*)d_in[4];
    const float* bo = (const float*)d_in[5];
    float* out = (float*)d_out;

    const int att_smem = (TP2*KQ2 + TP2*VP + 64*PP + 512) * (int)sizeof(float);
    cudaFuncSetAttribute(attn_mma, cudaFuncAttributeMaxDynamicSharedMemorySize, att_smem);

    // QKV projection: M=51200 -> 400 tiles of 128, N=1752 -> 14 tiles of 128
    gemm_tf32<0><<<dim3(14, 400), 256>>>(x, Wq, Wk, Wv, nullptr, nullptr);

    // attention: 512 threads (16 warps), one CTA per (b,h)
    attn_mma<<<BH_, 512, att_smem>>>();

    // output projection: N=584 -> 5 tiles
    gemm_tf32<1><<<dim3(5, 400), 256>>>(nullptr, Wo, nullptr, nullptr, bo, out);
}

// round 11
// speedup vs baseline: 1.5255x; 1.3432x over previous
#include <cuda_runtime.h>
#include <cuda_fp16.h>
#include <math.h>
#include <stdint.h>

// Problem constants
#define B_  256
#define T_  200
#define E_  584
#define H_  8
#define HS_ 73
#define HSP 74           // padded (even) head stride for fp16 pair loads
#define BH_ (B_*H_)      // 2048
#define M_  (B_*T_)      // 51200

// Scratch (allocation-free rule: __device__ globals; zero-initialized)
__device__ __half g_q[BH_*T_*HSP + 32];
__device__ __half g_k[BH_*T_*HSP + 32];
__device__ __half g_v[BH_*T_*HSP + 32];
__device__ float  g_att[M_*E_];

__device__ __forceinline__ uint32_t f2h2(float lo, float hi) {
    __half2 h = __floats2half2_rn(lo, hi);   // x = lo (low 16b), y = hi
    return *reinterpret_cast<uint32_t*>(&h);
}

__device__ __forceinline__ void mma_f16(float c[4],
                                        uint32_t a0, uint32_t a1, uint32_t a2, uint32_t a3,
                                        uint32_t b0, uint32_t b1) {
    asm volatile(
        "mma.sync.aligned.m16n8k16.row.col.f32.f16.f16.f32 "
        "{%0,%1,%2,%3}, {%4,%5,%6,%7}, {%8,%9}, {%0,%1,%2,%3};"
        : "+f"(c[0]), "+f"(c[1]), "+f"(c[2]), "+f"(c[3])
        : "r"(a0), "r"(a1), "r"(a2), "r"(a3), "r"(b0), "r"(b1));
}

__device__ __forceinline__ void ldm_x4(uint32_t& r0, uint32_t& r1,
                                       uint32_t& r2, uint32_t& r3, uint32_t a) {
    asm volatile("ldmatrix.sync.aligned.m8n8.x4.shared.b16 {%0,%1,%2,%3}, [%4];"
                 : "=r"(r0), "=r"(r1), "=r"(r2), "=r"(r3) : "r"(a));
}

__device__ __forceinline__ uint32_t s2u(const void* p) {
    return (uint32_t)__cvta_generic_to_shared(p);
}
__device__ __forceinline__ void named_bar(int id, int cnt) {
    asm volatile("bar.sync %0, %1;" :: "r"(id), "r"(cnt) : "memory");
}

// ---------------------------------------------------------------------------
// FP16 tensor-core GEMM:  C[m,n] = sum_k A[m,k] * B[n,k]   (f32 in/out)
// CTA 128x128, BK=32, 256 threads (8 warps, 4m x 2n), warp tile 32x64.
// smem fp16, pitch ROWPW=20 words/row (conflict-free ldmatrix).
// MODE 0: qkv projection  (A = x;     q scaled; fp16 scatter to g_q/g_k/g_v)
// MODE 1: out projection  (A = g_att; +bias -> out, f32)
// ---------------------------------------------------------------------------
#define ROWPW 20
#define BK    32
#define NSTG  19          // ceil(584/32)
#define TWW   (128*ROWPW)

template<int MODE>
__global__ __launch_bounds__(256, 2)
void gemm_f16(const float* __restrict__ Aarg,
              const float* __restrict__ B0,
              const float* __restrict__ B1,
              const float* __restrict__ B2,
              const float* __restrict__ bias,
              float* __restrict__ out)
{
    __shared__ uint32_t As[2][TWW];
    __shared__ uint32_t Bs[2][TWW];

    const float* A = (MODE == 0) ? Aarg : (const float*)g_att;

    const int tid  = threadIdx.x;
    const int lane = tid & 31;
    const int w    = tid >> 5;
    const int g    = lane >> 2;
    const int c    = lane & 3;
    const int wm   = w & 3;          // 4 m-warps, 32 rows each
    const int wn   = w >> 2;         // 2 n-warps, 64 cols each

    const int m0 = blockIdx.y * 128;
    const int n0 = blockIdx.x * 128;

    float acc[2][8][4];
#pragma unroll
    for (int mi = 0; mi < 2; mi++)
#pragma unroll
        for (int ni = 0; ni < 8; ni++)
#pragma unroll
            for (int r = 0; r < 4; r++) acc[mi][ni][r] = 0.f;

    // staging: thread owns row tid>>1, fp16 k-segment (tid&1)*16
    const int row  = tid >> 1;
    const int kseg = (tid & 1) * 16;

    const float* aptr = A + (size_t)(m0 + row) * E_ + kseg;

    const float* bptr;
    bool bval;
    {
        int gn = n0 + row;
        if (MODE == 0) {
            bval = gn < 3 * E_;
            int s = gn / E_; if (s > 2) s = 2;
            int l = bval ? gn - s * E_ : 0;
            const float* W = (s == 0) ? B0 : ((s == 1) ? B1 : B2);
            bptr = W + (size_t)l * E_;
        } else {
            bval = gn < E_;
            bptr = B0 + (size_t)(bval ? gn : 0) * E_;
        }
        bptr += kseg;
    }

    uint32_t* sA = &As[0][row * ROWPW + (tid & 1) * 8];
    uint32_t* sB = &Bs[0][row * ROWPW + (tid & 1) * 8];

    const int lr = lane & 15, lh = lane >> 4;
    uint32_t aAdr[2], bAdr[4];
#pragma unroll
    for (int mi = 0; mi < 2; mi++)
        aAdr[mi] = s2u(&As[0][0]) + (uint32_t)(((wm*32 + mi*16 + lr) * ROWPW + lh*4) * 4);
#pragma unroll
    for (int np = 0; np < 4; np++)
        bAdr[np] = s2u(&Bs[0][0]) + (uint32_t)(((wn*64 + np*16 + lr) * ROWPW + lh*4) * 4);
    const uint32_t BUFB = TWW * 4;

    const float4 z4 = make_float4(0.f, 0.f, 0.f, 0.f);

    // load 16 f32 (k) for given stage; convert; store 2 x uint4
    auto stage_store = [&](int s, uint32_t* dA, uint32_t* dB) {
        const int k0 = s * BK;
        float4 va[4], vb[4];
#pragma unroll
        for (int j = 0; j < 4; j++) {
            const bool v = (k0 + kseg + j * 4) < E_;
            va[j] = v ? *(const float4*)(aptr + k0 + j * 4) : z4;
            vb[j] = (v && bval) ? *(const float4*)(bptr + k0 + j * 4) : z4;
        }
        uint4 u0 = make_uint4(f2h2(va[0].x, va[0].y), f2h2(va[0].z, va[0].w),
                              f2h2(va[1].x, va[1].y), f2h2(va[1].z, va[1].w));
        uint4 u1 = make_uint4(f2h2(va[2].x, va[2].y), f2h2(va[2].z, va[2].w),
                              f2h2(va[3].x, va[3].y), f2h2(va[3].z, va[3].w));
        *(uint4*)dA       = u0;
        *(uint4*)(dA + 4) = u1;
        uint4 w0 = make_uint4(f2h2(vb[0].x, vb[0].y), f2h2(vb[0].z, vb[0].w),
                              f2h2(vb[1].x, vb[1].y), f2h2(vb[1].z, vb[1].w));
        uint4 w1 = make_uint4(f2h2(vb[2].x, vb[2].y), f2h2(vb[2].z, vb[2].w),
                              f2h2(vb[3].x, vb[3].y), f2h2(vb[3].z, vb[3].w));
        *(uint4*)dB       = w0;
        *(uint4*)(dB + 4) = w1;
    };

    stage_store(0, sA, sB);
    __syncthreads();

#pragma unroll 1
    for (int s = 0; s < NSTG; s++) {
        const int buf = s & 1;
        const bool more = (s + 1 < NSTG);

        const uint32_t kb = buf * BUFB;
#pragma unroll
        for (int t16 = 0; t16 < 2; t16++) {
            const uint32_t ko = kb + t16 * 32;   // 8 words = 16 fp16 per k16
            uint32_t a[2][4], bm[4][4];
#pragma unroll
            for (int mi = 0; mi < 2; mi++)
                ldm_x4(a[mi][0], a[mi][1], a[mi][2], a[mi][3], aAdr[mi] + ko);
#pragma unroll
            for (int np = 0; np < 4; np++)
                ldm_x4(bm[np][0], bm[np][1], bm[np][2], bm[np][3], bAdr[np] + ko);
#pragma unroll
            for (int mi = 0; mi < 2; mi++)
#pragma unroll
                for (int np = 0; np < 4; np++) {
                    mma_f16(acc[mi][2*np],   a[mi][0], a[mi][1], a[mi][2], a[mi][3],
                            bm[np][0], bm[np][2]);
                    mma_f16(acc[mi][2*np+1], a[mi][0], a[mi][1], a[mi][2], a[mi][3],
                            bm[np][1], bm[np][3]);
                }
        }

        if (more)
            stage_store(s + 1, sA + (buf ^ 1) * TWW, sB + (buf ^ 1) * TWW);
        __syncthreads();
    }

    // ---- epilogue -----------------------------------------------------------
    const float scale = rsqrtf((float)E_);
#pragma unroll
    for (int mi = 0; mi < 2; mi++) {
#pragma unroll
        for (int ni = 0; ni < 8; ni++) {
#pragma unroll
            for (int r = 0; r < 4; r++) {
                const int m = m0 + wm * 32 + mi * 16 + g + ((r >= 2) ? 8 : 0);
                const int n = n0 + wn * 64 + ni * 8 + 2 * c + (r & 1);
                const float v = acc[mi][ni][r];
                if (MODE == 0) {
                    if (n < 3 * E_) {
                        const int sidx = n / E_;
                        const int l    = n - sidx * E_;
                        const int hh   = l / HS_;
                        const int f    = l - hh * HS_;
                        const int bb   = m / T_;
                        const int t    = m - bb * T_;
                        __half* dst = (sidx == 0) ? g_q : ((sidx == 1) ? g_k : g_v);
                        const float vv = (sidx == 0) ? v * scale : v;
                        dst[((size_t)(bb * H_ + hh) * T_ + t) * HSP + f] = __float2half(vv);
                    }
                } else {
                    if (n < E_)
                        out[(size_t)m * E_ + n] = v + bias[n];
                }
            }
        }
    }
}

// ---------------------------------------------------------------------------
// FP16 tensor-core attention: 512 threads, 4 teams (wm) x 4 warps (wn).
// Ks  [208 rows (s), pitch 44 words]  fp16 n-major  (k = head dim, 80 padded)
// Vt  [80 rows (f),  pitch 108 words] fp16 n-major  (k = s, 208 padded)
// Pt  [64 rows (t),  pitch 108 words] fp16
// Q fragments: direct 32-bit gmem loads (scale pre-folded into g_q).
// ---------------------------------------------------------------------------
#define KSW 44
#define VTW 108
#define PTW 108
#define ATT_WORDS (208*KSW + 80*VTW + 64*PTW + 512)

__global__ __launch_bounds__(512, 1)
void attn_mma()
{
    extern __shared__ uint32_t smu[];
    uint32_t* Ks = smu;                    // [208][44]
    uint32_t* Vt = Ks + 208*KSW;           // [80][108]
    uint32_t* Pt = Vt + 80*VTW;            // [64][108]
    float* pmax  = (float*)(Pt + 64*PTW);  // [64][4]
    float* psum  = pmax + 256;             // [64][4]

    const int bh   = blockIdx.x;
    const int tid  = threadIdx.x;
    const int lane = tid & 31;
    const int w    = tid >> 5;
    const int g    = lane >> 2;
    const int c    = lane & 3;
    const int wm   = w & 3;
    const int wn   = w >> 2;
    const int b    = bh / H_;
    const int h    = bh - b * H_;
    const int barid = 1 + wm;

    const __half* qg = g_q + (size_t)bh * T_ * HSP;
    const __half* kg = g_k + (size_t)bh * T_ * HSP;
    const __half* vg = g_v + (size_t)bh * T_ * HSP;

    // ---- K: copy pairs (zero-padded to 208 x 80) ----------------------------
    for (int i = tid; i < 208*40; i += 512) {
        const int s = i / 40, f2 = i - s * 40;
        uint32_t val = 0;
        if (s < T_) {
            if (2*f2 + 1 < HS_) val = *(const uint32_t*)(kg + (size_t)s*HSP + 2*f2);
            else if (2*f2 < HS_) {
                __half lo = kg[(size_t)s*HSP + 2*f2];
                val = (uint32_t)__half_as_ushort(lo);
            }
        }
        Ks[s*KSW + f2] = val;
    }
    // ---- V transposed: Vt[f][s] pairs along s ------------------------------
    for (int i = tid; i < 80*104; i += 512) {
        const int f = i / 104, s2 = i - f * 104;
        __half lo = (2*s2   < T_ && f < HS_) ? vg[(size_t)(2*s2  )*HSP + f] : __ushort_as_half((unsigned short)0);
        __half hi = (2*s2+1 < T_ && f < HS_) ? vg[(size_t)(2*s2+1)*HSP + f] : __ushort_as_half((unsigned short)0);
        __half2 p = __halves2half2(lo, hi);
        Vt[f*VTW + s2] = *reinterpret_cast<uint32_t*>(&p);
    }
    __syncthreads();   // only CTA-wide barrier

    const int mr = wm * 16;
    const int rq_lo = mr + g;
    const int rq_hi = mr + g + 8;

    const int lr = lane & 15, lh = lane >> 4;
    const uint32_t kBase = s2u(Ks) + (uint32_t)((lr * KSW + lh * 4) * 4);
    const uint32_t pBase = s2u(Pt) + (uint32_t)(((mr + lr) * PTW + lh * 4) * 4);

#pragma unroll 1
    for (int t0 = 0; t0 < T_; t0 += 64) {
        const int thi = t0 + mr + 15;

        const int row_lo = (t0 + rq_lo < T_) ? (t0 + rq_lo) : (T_ - 1);
        const int row_hi = (t0 + rq_hi < T_) ? (t0 + rq_hi) : (T_ - 1);
        const __half* qlo = qg + (size_t)row_lo * HSP;
        const __half* qhi = qg + (size_t)row_hi * HSP;

        float acc[4][2][4];
#pragma unroll
        for (int u = 0; u < 4; u++)
#pragma unroll
            for (int e = 0; e < 2; e++)
#pragma unroll
                for (int r = 0; r < 4; r++) acc[u][e][r] = 0.f;

        // ---- S = Q.K^T over k=0..79 (5 k16 steps) ---------------------------
#pragma unroll
        for (int ks = 0; ks < 80; ks += 16) {
            const int k0 = ks + 2*c;       // <= 70, pairs aligned
            const int k1 = k0 + 8;         // may overrun into padding: K is zero there
            const uint32_t a0 = *(const uint32_t*)(qlo + k0);
            const uint32_t a1 = *(const uint32_t*)(qhi + k0);
            const uint32_t a2 = *(const uint32_t*)(qlo + k1);
            const uint32_t a3 = *(const uint32_t*)(qhi + k1);
#pragma unroll
            for (int u = 0; u < 4; u++) {
                const int chunk = 4*u + wn;
                const int cb = chunk * 16;
                if (chunk < 13 && cb <= thi) {
                    uint32_t b0, b1, b2, b3;
                    ldm_x4(b0, b1, b2, b3, kBase + (uint32_t)(cb * (KSW*4) + ks * 2));
                    mma_f16(acc[u][0], a0, a1, a2, a3, b0, b2);
                    mma_f16(acc[u][1], a0, a1, a2, a3, b1, b3);
                }
            }
        }

        // ---- softmax (team-local) -------------------------------------------
        const int t_lo = t0 + rq_lo;
        const int t_hi = t0 + rq_hi;

        float mlo = -1e30f, mhi = -1e30f;
#pragma unroll
        for (int u = 0; u < 4; u++)
#pragma unroll
            for (int e = 0; e < 2; e++) {
                const int s0 = (4*u + wn)*16 + e*8 + 2*c;
                const int s1 = s0 + 1;
                if ((s0 <= t_lo) && (s0 < T_) && (t_lo < T_)) mlo = fmaxf(mlo, acc[u][e][0]);
                if ((s1 <= t_lo) && (s1 < T_) && (t_lo < T_)) mlo = fmaxf(mlo, acc[u][e][1]);
                if ((s0 <= t_hi) && (s0 < T_) && (t_hi < T_)) mhi = fmaxf(mhi, acc[u][e][2]);
                if ((s1 <= t_hi) && (s1 < T_) && (t_hi < T_)) mhi = fmaxf(mhi, acc[u][e][3]);
            }
#pragma unroll
        for (int off = 1; off <= 2; off <<= 1) {
            mlo = fmaxf(mlo, __shfl_xor_sync(0xffffffffu, mlo, off));
            mhi = fmaxf(mhi, __shfl_xor_sync(0xffffffffu, mhi, off));
        }
        if (c == 0) {
            pmax[rq_lo*4 + wn] = mlo;
            pmax[rq_hi*4 + wn] = mhi;
        }
        named_bar(barid, 128);
        const float gmlo = fmaxf(fmaxf(pmax[rq_lo*4], pmax[rq_lo*4+1]),
                                 fmaxf(pmax[rq_lo*4+2], pmax[rq_lo*4+3]));
        const float gmhi = fmaxf(fmaxf(pmax[rq_hi*4], pmax[rq_hi*4+1]),
                                 fmaxf(pmax[rq_hi*4+2], pmax[rq_hi*4+3]));

        float slo = 0.f, shi = 0.f;
#pragma unroll
        for (int u = 0; u < 4; u++)
#pragma unroll
            for (int e = 0; e < 2; e++) {
                const int s0 = (4*u + wn)*16 + e*8 + 2*c;
                const int s1 = s0 + 1;
                const bool ok0l = (s0 <= t_lo) && (s0 < T_) && (t_lo < T_);
                const bool ok1l = (s1 <= t_lo) && (s1 < T_) && (t_lo < T_);
                const bool ok0h = (s0 <= t_hi) && (s0 < T_) && (t_hi < T_);
                const bool ok1h = (s1 <= t_hi) && (s1 < T_) && (t_hi < T_);
                float e0 = ok0l ? __expf(acc[u][e][0] - gmlo) : 0.f;
                float e1 = ok1l ? __expf(acc[u][e][1] - gmlo) : 0.f;
                float e2 = ok0h ? __expf(acc[u][e][2] - gmhi) : 0.f;
                float e3 = ok1h ? __expf(acc[u][e][3] - gmhi) : 0.f;
                acc[u][e][0] = e0; acc[u][e][1] = e1;
                acc[u][e][2] = e2; acc[u][e][3] = e3;
                slo += e0 + e1;  shi += e2 + e3;
            }
#pragma unroll
        for (int off = 1; off <= 2; off <<= 1) {
            slo += __shfl_xor_sync(0xffffffffu, slo, off);
            shi += __shfl_xor_sync(0xffffffffu, shi, off);
        }
        if (c == 0) {
            psum[rq_lo*4 + wn] = slo;
            psum[rq_hi*4 + wn] = shi;
        }
        named_bar(barid, 128);
        const float tlo  = psum[rq_lo*4] + psum[rq_lo*4+1] + psum[rq_lo*4+2] + psum[rq_lo*4+3];
        const float thi2 = psum[rq_hi*4] + psum[rq_hi*4+1] + psum[rq_hi*4+2] + psum[rq_hi*4+3];
        const float rlo = (tlo  > 0.f) ? (1.f / tlo)  : 0.f;
        const float rhi = (thi2 > 0.f) ? (1.f / thi2) : 0.f;

        // ---- write normalized P (fp16) --------------------------------------
#pragma unroll
        for (int u = 0; u < 4; u++) {
            const int chunk = 4*u + wn;
            if (chunk < 13) {
#pragma unroll
                for (int e = 0; e < 2; e++) {
                    const int cw = chunk*8 + e*4 + c;   // word index (col/2)
                    Pt[rq_lo*PTW + cw] = f2h2(acc[u][e][0]*rlo, acc[u][e][1]*rlo);
                    Pt[rq_hi*PTW + cw] = f2h2(acc[u][e][2]*rhi, acc[u][e][3]*rhi);
                }
            }
        }
        named_bar(barid, 128);

        // ---- O = P.V : f-tiles nt = wn + 4j ---------------------------------
        float o[3][4];
#pragma unroll
        for (int j = 0; j < 3; j++)
#pragma unroll
            for (int r = 0; r < 4; r++) o[j][r] = 0.f;

        const int kcap    = (thi < T_-1) ? thi : (T_-1);
        const int ksb_end = kcap >> 4;
#pragma unroll 1
        for (int ksb = 0; ksb <= ksb_end; ksb++) {
            uint32_t a0, a1, a2, a3;
            ldm_x4(a0, a1, a2, a3, pBase + (uint32_t)(ksb * 32));
#pragma unroll
            for (int j = 0; j < 3; j++) {
                const int nt = wn + 4*j;
                if (nt < 10) {
                    const uint32_t b0 = Vt[(nt*8 + g)*VTW + ksb*8 + c];
                    const uint32_t b1 = Vt[(nt*8 + g)*VTW + ksb*8 + c + 4];
                    mma_f16(o[j], a0, a1, a2, a3, b0, b1);
                }
            }
        }

#pragma unroll
        for (int j = 0; j < 3; j++) {
            const int nt = wn + 4*j;
            if (nt < 10) {
#pragma unroll
                for (int r = 0; r < 4; r++) {
                    const int t = t0 + mr + g + ((r >= 2) ? 8 : 0);
                    const int f = nt*8 + 2*c + (r & 1);
                    if (t < T_ && f < HS_)
                        g_att[((size_t)(b*T_ + t))*E_ + h*HS_ + f] = o[j][r];
                }
            }
        }
        named_bar(barid, 128);
    }
}

// ---------------------------------------------------------------------------
extern "C" void kernel_launch(void* const* d_in, const int* in_sizes, int n_in,
                              void* d_out, int out_size)
{
    const float* x  = (const float*)d_in[0];
    const float* Wq = (const float*)d_in[1];
    const float* Wk = (const float*)d_in[2];
    const float* Wv = (const float*)d_in[3];
    const float* Wo = (const float*)d_in[4];
    const float* bo = (const float*)d_in[5];
    float* out = (float*)d_out;

    const int att_smem = ATT_WORDS * (int)sizeof(uint32_t);   // ~100.9 KB
    cudaFuncSetAttribute(attn_mma, cudaFuncAttributeMaxDynamicSharedMemorySize, att_smem);

    // QKV projection: M=51200 -> 400 tiles of 128, N=1752 -> 14 tiles of 128
    gemm_f16<0><<<dim3(14, 400), 256>>>(x, Wq, Wk, Wv, nullptr, nullptr);

    // attention: 512 threads, one CTA per (b,h)
    attn_mma<<<BH_, 512, att_smem>>>();

    // output projection: N=584 -> 5 tiles
    gemm_f16<1><<<dim3(5, 400), 256>>>(nullptr, Wo, nullptr, nullptr, bo, out);
}

// round 12
// speedup vs baseline: 2.0132x; 1.3197x over previous
#include <cuda_runtime.h>
#include <cuda_fp16.h>
#include <math.h>
#include <stdint.h>

// Problem constants
#define B_  256
#define T_  200
#define E_  584
#define H_  8
#define HS_ 73
#define HSP 74           // padded head stride (halves)
#define XP  592          // padded fp16 row stride for x / weights (16B multiple)
#define BH_ (B_*H_)      // 2048
#define M_  (B_*T_)      // 51200

// Scratch (allocation-free rule: __device__ globals; zero-init at load)
__device__ __half g_q[BH_*T_*HSP + 32];
__device__ __half g_k[BH_*T_*HSP + 32];
__device__ __half g_v[BH_*T_*HSP + 32];
__device__ __half g_atth[M_*E_ + 32];
__device__ __half g_xh[(size_t)M_*XP];
__device__ __half g_wh[1752*XP];      // Wq|Wk|Wv rows stacked
__device__ __half g_woh[E_*XP];

__device__ __forceinline__ uint32_t f2h2(float lo, float hi) {
    __half2 h = __floats2half2_rn(lo, hi);
    return *reinterpret_cast<uint32_t*>(&h);
}

__device__ __forceinline__ void mma_f16(float c[4],
                                        uint32_t a0, uint32_t a1, uint32_t a2, uint32_t a3,
                                        uint32_t b0, uint32_t b1) {
    asm volatile(
        "mma.sync.aligned.m16n8k16.row.col.f32.f16.f16.f32 "
        "{%0,%1,%2,%3}, {%4,%5,%6,%7}, {%8,%9}, {%0,%1,%2,%3};"
        : "+f"(c[0]), "+f"(c[1]), "+f"(c[2]), "+f"(c[3])
        : "r"(a0), "r"(a1), "r"(a2), "r"(a3), "r"(b0), "r"(b1));
}

__device__ __forceinline__ void ldm_x4(uint32_t& r0, uint32_t& r1,
                                       uint32_t& r2, uint32_t& r3, uint32_t a) {
    asm volatile("ldmatrix.sync.aligned.m8n8.x4.shared.b16 {%0,%1,%2,%3}, [%4];"
                 : "=r"(r0), "=r"(r1), "=r"(r2), "=r"(r3) : "r"(a));
}

__device__ __forceinline__ uint32_t s2u(const void* p) {
    return (uint32_t)__cvta_generic_to_shared(p);
}
__device__ __forceinline__ void cp16(uint32_t d, const void* s, bool v) {
    asm volatile("cp.async.ca.shared.global [%0], [%1], 16, %2;"
                 :: "r"(d), "l"(s), "r"(v ? 16 : 0));
}
__device__ __forceinline__ void cp_commit() { asm volatile("cp.async.commit_group;"); }
__device__ __forceinline__ void cp_wait1()  { asm volatile("cp.async.wait_group 1;"); }
__device__ __forceinline__ void named_bar(int id, int cnt) {
    asm volatile("bar.sync %0, %1;" :: "r"(id), "r"(cnt) : "memory");
}

// ---------------------------------------------------------------------------
// Conversion prep kernels (fp32 -> padded fp16)
// ---------------------------------------------------------------------------
__global__ void cvt_x(const float* __restrict__ x) {
    const int W = XP / 2;   // 296 words per row
    int i = blockIdx.x * 256 + threadIdx.x;
    if (i >= M_ * W) return;
    int m = i / W, c2 = (i - m * W) * 2;
    float lo = (c2     < E_) ? x[(size_t)m * E_ + c2]     : 0.f;
    float hi = (c2 + 1 < E_) ? x[(size_t)m * E_ + c2 + 1] : 0.f;
    reinterpret_cast<uint32_t*>(g_xh)[i] = f2h2(lo, hi);
}

__global__ void cvt_w(const float* __restrict__ Wq, const float* __restrict__ Wk,
                      const float* __restrict__ Wv, const float* __restrict__ Wo) {
    const int W = XP / 2;
    int i = blockIdx.x * 256 + threadIdx.x;
    if (i >= (1752 + E_) * W) return;
    int row = i / W, c2 = (i - row * W) * 2;
    const float* src;
    uint32_t* dst;
    int r;
    if (row < 1752) {
        int s = row / E_;
        r = row - s * E_;
        src = (s == 0) ? Wq : ((s == 1) ? Wk : Wv);
        dst = reinterpret_cast<uint32_t*>(g_wh) + (size_t)row * W;
    } else {
        r = row - 1752;
        src = Wo;
        dst = reinterpret_cast<uint32_t*>(g_woh) + (size_t)r * W;
    }
    float lo = (c2     < E_) ? src[(size_t)r * E_ + c2]     : 0.f;
    float hi = (c2 + 1 < E_) ? src[(size_t)r * E_ + c2 + 1] : 0.f;
    dst[i - row * W] = f2h2(lo, hi);
}

// ---------------------------------------------------------------------------
// FP16 GEMM with cp.async 3-stage pipeline:  C[m,n] = sum_k A[m,k]*B[n,k]
// CTA 128x128, BK=32 (halves), 256 threads (8 warps, 4m x 2n), warp 32x64.
// smem fp16, pitch ROWPW=20 words/row (conflict-free ldmatrix).
// MODE 0: qkv (A=g_xh/XP, B=g_wh/XP; fp16 scatter, q scaled)
// MODE 1: out (A=g_atth/E_, B=g_woh/XP; +bias -> f32 out)
// ---------------------------------------------------------------------------
#define ROWPW  20
#define BK     32
#define STAGES 3
#define NSTG   19
#define TWW    (128*ROWPW)
#define GSMEM  (STAGES*2*TWW*4)

template<int MODE>
__global__ __launch_bounds__(256, 2)
void gemm_f16(const float* __restrict__ bias, float* __restrict__ out)
{
    extern __shared__ uint32_t gsm[];
    uint32_t* As = gsm;               // [STAGES][TWW]
    uint32_t* Bs = gsm + STAGES*TWW;  // [STAGES][TWW]

    const __half* A = (MODE == 0) ? g_xh  : g_atth;
    const __half* Bm = (MODE == 0) ? g_wh : g_woh;
    const int strideA = (MODE == 0) ? XP : E_;
    const int availA  = (MODE == 0) ? XP : E_;
    const int Ntot    = (MODE == 0) ? 1752 : E_;

    const int tid  = threadIdx.x;
    const int lane = tid & 31;
    const int w    = tid >> 5;
    const int g    = lane >> 2;
    const int c    = lane & 3;
    const int wm   = w & 3;
    const int wn   = w >> 2;

    const int m0 = blockIdx.y * 128;
    const int n0 = blockIdx.x * 128;

    float acc[2][8][4];
#pragma unroll
    for (int mi = 0; mi < 2; mi++)
#pragma unroll
        for (int ni = 0; ni < 8; ni++)
#pragma unroll
            for (int r = 0; r < 4; r++) acc[mi][ni][r] = 0.f;

    // staging: thread owns row tid>>1, halves segment (tid&1)*16
    const int row  = tid >> 1;
    const int kseg = (tid & 1) * 16;

    const __half* aptr = A + (size_t)(m0 + row) * strideA + kseg;
    const int gn = n0 + row;
    const bool bval = gn < Ntot;
    const __half* bptr = Bm + (size_t)(bval ? gn : 0) * XP + kseg;

    const uint32_t a_s0 = s2u(&As[row * ROWPW + (tid & 1) * 8]);
    const uint32_t b_s0 = s2u(&Bs[row * ROWPW + (tid & 1) * 8]);
    const uint32_t stage_bytes = TWW * 4;

    auto issue = [&](int s) {
        if (s < NSTG) {
            const int kb = s * BK;
            const int slot = s % STAGES;
            const uint32_t ad = a_s0 + slot * stage_bytes;
            const uint32_t bd = b_s0 + slot * stage_bytes;
            const int kk0 = kb + kseg;
            cp16(ad,      aptr + kb,     kk0 + 8  <= availA);
            cp16(ad + 16, aptr + kb + 8, kk0 + 16 <= availA);
            cp16(bd,      bptr + kb,     bval && (kk0 + 8  <= XP));
            cp16(bd + 16, bptr + kb + 8, bval && (kk0 + 16 <= XP));
        }
        cp_commit();
    };

    const int lr = lane & 15, lh = lane >> 4;
    uint32_t aAdr[2], bAdr[4];
#pragma unroll
    for (int mi = 0; mi < 2; mi++)
        aAdr[mi] = s2u(&As[0]) + (uint32_t)(((wm*32 + mi*16 + lr) * ROWPW + lh*4) * 4);
#pragma unroll
    for (int np = 0; np < 4; np++)
        bAdr[np] = s2u(&Bs[0]) + (uint32_t)(((wn*64 + np*16 + lr) * ROWPW + lh*4) * 4);

    issue(0);
    issue(1);

#pragma unroll 1
    for (int s = 0; s < NSTG; s++) {
        cp_wait1();
        __syncthreads();
        issue(s + 2);

        const uint32_t kb = (uint32_t)(s % STAGES) * stage_bytes;
#pragma unroll
        for (int t16 = 0; t16 < 2; t16++) {
            const uint32_t ko = kb + t16 * 32;   // 16 halves = 32 bytes
            uint32_t a[2][4], bm[4][4];
#pragma unroll
            for (int mi = 0; mi < 2; mi++)
                ldm_x4(a[mi][0], a[mi][1], a[mi][2], a[mi][3], aAdr[mi] + ko);
#pragma unroll
            for (int np = 0; np < 4; np++)
                ldm_x4(bm[np][0], bm[np][1], bm[np][2], bm[np][3], bAdr[np] + ko);
#pragma unroll
            for (int mi = 0; mi < 2; mi++)
#pragma unroll
                for (int np = 0; np < 4; np++) {
                    mma_f16(acc[mi][2*np],   a[mi][0], a[mi][1], a[mi][2], a[mi][3],
                            bm[np][0], bm[np][2]);
                    mma_f16(acc[mi][2*np+1], a[mi][0], a[mi][1], a[mi][2], a[mi][3],
                            bm[np][1], bm[np][3]);
                }
        }
    }

    // ---- epilogue -----------------------------------------------------------
    const float scale = rsqrtf((float)E_);
#pragma unroll
    for (int mi = 0; mi < 2; mi++) {
#pragma unroll
        for (int ni = 0; ni < 8; ni++) {
#pragma unroll
            for (int r = 0; r < 4; r++) {
                const int m = m0 + wm * 32 + mi * 16 + g + ((r >= 2) ? 8 : 0);
                const int n = n0 + wn * 64 + ni * 8 + 2 * c + (r & 1);
                const float v = acc[mi][ni][r];
                if (MODE == 0) {
                    if (n < 3 * E_) {
                        const int sidx = n / E_;
                        const int l    = n - sidx * E_;
                        const int hh   = l / HS_;
                        const int f    = l - hh * HS_;
                        const int bb   = m / T_;
                        const int t    = m - bb * T_;
                        __half* dst = (sidx == 0) ? g_q : ((sidx == 1) ? g_k : g_v);
                        const float vv = (sidx == 0) ? v * scale : v;
                        dst[((size_t)(bb * H_ + hh) * T_ + t) * HSP + f] = __float2half(vv);
                    }
                } else {
                    if (n < E_)
                        out[(size_t)m * E_ + n] = v + bias[n];
                }
            }
        }
    }
}

// ---------------------------------------------------------------------------
// FP16 attention (R11, unchanged except fp16 output to g_atth)
// ---------------------------------------------------------------------------
#define KSW 44
#define VTW 108
#define PTW 108
#define ATT_WORDS (208*KSW + 80*VTW + 64*PTW + 512)

__global__ __launch_bounds__(512, 1)
void attn_mma()
{
    extern __shared__ uint32_t smu[];
    uint32_t* Ks = smu;                    // [208][44]
    uint32_t* Vt = Ks + 208*KSW;           // [80][108]
    uint32_t* Pt = Vt + 80*VTW;            // [64][108]
    float* pmax  = (float*)(Pt + 64*PTW);  // [64][4]
    float* psum  = pmax + 256;             // [64][4]

    const int bh   = blockIdx.x;
    const int tid  = threadIdx.x;
    const int lane = tid & 31;
    const int w    = tid >> 5;
    const int g    = lane >> 2;
    const int c    = lane & 3;
    const int wm   = w & 3;
    const int wn   = w >> 2;
    const int b    = bh / H_;
    const int h    = bh - b * H_;
    const int barid = 1 + wm;

    const __half* qg = g_q + (size_t)bh * T_ * HSP;
    const __half* kg = g_k + (size_t)bh * T_ * HSP;
    const __half* vg = g_v + (size_t)bh * T_ * HSP;

    for (int i = tid; i < 208*40; i += 512) {
        const int s = i / 40, f2 = i - s * 40;
        uint32_t val = 0;
        if (s < T_) {
            if (2*f2 + 1 < HS_) val = *(const uint32_t*)(kg + (size_t)s*HSP + 2*f2);
            else if (2*f2 < HS_) val = (uint32_t)__half_as_ushort(kg[(size_t)s*HSP + 2*f2]);
        }
        Ks[s*KSW + f2] = val;
    }
    for (int i = tid; i < 80*104; i += 512) {
        const int f = i / 104, s2 = i - f * 104;
        __half lo = (2*s2   < T_ && f < HS_) ? vg[(size_t)(2*s2  )*HSP + f] : __ushort_as_half((unsigned short)0);
        __half hi = (2*s2+1 < T_ && f < HS_) ? vg[(size_t)(2*s2+1)*HSP + f] : __ushort_as_half((unsigned short)0);
        __half2 p = __halves2half2(lo, hi);
        Vt[f*VTW + s2] = *reinterpret_cast<uint32_t*>(&p);
    }
    __syncthreads();

    const int mr = wm * 16;
    const int rq_lo = mr + g;
    const int rq_hi = mr + g + 8;

    const int lr = lane & 15, lh = lane >> 4;
    const uint32_t kBase = s2u(Ks) + (uint32_t)((lr * KSW + lh * 4) * 4);
    const uint32_t pBase = s2u(Pt) + (uint32_t)(((mr + lr) * PTW + lh * 4) * 4);

#pragma unroll 1
    for (int t0 = 0; t0 < T_; t0 += 64) {
        const int thi = t0 + mr + 15;

        const int row_lo = (t0 + rq_lo < T_) ? (t0 + rq_lo) : (T_ - 1);
        const int row_hi = (t0 + rq_hi < T_) ? (t0 + rq_hi) : (T_ - 1);
        const __half* qlo = qg + (size_t)row_lo * HSP;
        const __half* qhi = qg + (size_t)row_hi * HSP;

        float acc[4][2][4];
#pragma unroll
        for (int u = 0; u < 4; u++)
#pragma unroll
            for (int e = 0; e < 2; e++)
#pragma unroll
                for (int r = 0; r < 4; r++) acc[u][e][r] = 0.f;

#pragma unroll
        for (int ks = 0; ks < 80; ks += 16) {
            const int k0 = ks + 2*c;
            const int k1 = k0 + 8;
            const uint32_t a0 = *(const uint32_t*)(qlo + k0);
            const uint32_t a1 = *(const uint32_t*)(qhi + k0);
            const uint32_t a2 = *(const uint32_t*)(qlo + k1);
            const uint32_t a3 = *(const uint32_t*)(qhi + k1);
#pragma unroll
            for (int u = 0; u < 4; u++) {
                const int chunk = 4*u + wn;
                const int cb = chunk * 16;
                if (chunk < 13 && cb <= thi) {
                    uint32_t b0, b1, b2, b3;
                    ldm_x4(b0, b1, b2, b3, kBase + (uint32_t)(cb * (KSW*4) + ks * 2));
                    mma_f16(acc[u][0], a0, a1, a2, a3, b0, b2);
                    mma_f16(acc[u][1], a0, a1, a2, a3, b1, b3);
                }
            }
        }

        const int t_lo = t0 + rq_lo;
        const int t_hi = t0 + rq_hi;

        float mlo = -1e30f, mhi = -1e30f;
#pragma unroll
        for (int u = 0; u < 4; u++)
#pragma unroll
            for (int e = 0; e < 2; e++) {
                const int s0 = (4*u + wn)*16 + e*8 + 2*c;
                const int s1 = s0 + 1;
                if ((s0 <= t_lo) && (s0 < T_) && (t_lo < T_)) mlo = fmaxf(mlo, acc[u][e][0]);
                if ((s1 <= t_lo) && (s1 < T_) && (t_lo < T_)) mlo = fmaxf(mlo, acc[u][e][1]);
                if ((s0 <= t_hi) && (s0 < T_) && (t_hi < T_)) mhi = fmaxf(mhi, acc[u][e][2]);
                if ((s1 <= t_hi) && (s1 < T_) && (t_hi < T_)) mhi = fmaxf(mhi, acc[u][e][3]);
            }
#pragma unroll
        for (int off = 1; off <= 2; off <<= 1) {
            mlo = fmaxf(mlo, __shfl_xor_sync(0xffffffffu, mlo, off));
            mhi = fmaxf(mhi, __shfl_xor_sync(0xffffffffu, mhi, off));
        }
        if (c == 0) {
            pmax[rq_lo*4 + wn] = mlo;
            pmax[rq_hi*4 + wn] = mhi;
        }
        named_bar(barid, 128);
        const float gmlo = fmaxf(fmaxf(pmax[rq_lo*4], pmax[rq_lo*4+1]),
                                 fmaxf(pmax[rq_lo*4+2], pmax[rq_lo*4+3]));
        const float gmhi = fmaxf(fmaxf(pmax[rq_hi*4], pmax[rq_hi*4+1]),
                                 fmaxf(pmax[rq_hi*4+2], pmax[rq_hi*4+3]));

        float slo = 0.f, shi = 0.f;
#pragma unroll
        for (int u = 0; u < 4; u++)
#pragma unroll
            for (int e = 0; e < 2; e++) {
                const int s0 = (4*u + wn)*16 + e*8 + 2*c;
                const int s1 = s0 + 1;
                const bool ok0l = (s0 <= t_lo) && (s0 < T_) && (t_lo < T_);
                const bool ok1l = (s1 <= t_lo) && (s1 < T_) && (t_lo < T_);
                const bool ok0h = (s0 <= t_hi) && (s0 < T_) && (t_hi < T_);
                const bool ok1h = (s1 <= t_hi) && (s1 < T_) && (t_hi < T_);
                float e0 = ok0l ? __expf(acc[u][e][0] - gmlo) : 0.f;
                float e1 = ok1l ? __expf(acc[u][e][1] - gmlo) : 0.f;
                float e2 = ok0h ? __expf(acc[u][e][2] - gmhi) : 0.f;
                float e3 = ok1h ? __expf(acc[u][e][3] - gmhi) : 0.f;
                acc[u][e][0] = e0; acc[u][e][1] = e1;
                acc[u][e][2] = e2; acc[u][e][3] = e3;
                slo += e0 + e1;  shi += e2 + e3;
            }
#pragma unroll
        for (int off = 1; off <= 2; off <<= 1) {
            slo += __shfl_xor_sync(0xffffffffu, slo, off);
            shi += __shfl_xor_sync(0xffffffffu, shi, off);
        }
        if (c == 0) {
            psum[rq_lo*4 + wn] = slo;
            psum[rq_hi*4 + wn] = shi;
        }
        named_bar(barid, 128);
        const float tlo  = psum[rq_lo*4] + psum[rq_lo*4+1] + psum[rq_lo*4+2] + psum[rq_lo*4+3];
        const float thi2 = psum[rq_hi*4] + psum[rq_hi*4+1] + psum[rq_hi*4+2] + psum[rq_hi*4+3];
        const float rlo = (tlo  > 0.f) ? (1.f / tlo)  : 0.f;
        const float rhi = (thi2 > 0.f) ? (1.f / thi2) : 0.f;

#pragma unroll
        for (int u = 0; u < 4; u++) {
            const int chunk = 4*u + wn;
            if (chunk < 13) {
#pragma unroll
                for (int e = 0; e < 2; e++) {
                    const int cw = chunk*8 + e*4 + c;
                    Pt[rq_lo*PTW + cw] = f2h2(acc[u][e][0]*rlo, acc[u][e][1]*rlo);
                    Pt[rq_hi*PTW + cw] = f2h2(acc[u][e][2]*rhi, acc[u][e][3]*rhi);
                }
            }
        }
        named_bar(barid, 128);

        float o[3][4];
#pragma unroll
        for (int j = 0; j < 3; j++)
#pragma unroll
            for (int r = 0; r < 4; r++) o[j][r] = 0.f;

        const int kcap    = (thi < T_-1) ? thi : (T_-1);
        const int ksb_end = kcap >> 4;
#pragma unroll 1
        for (int ksb = 0; ksb <= ksb_end; ksb++) {
            uint32_t a0, a1, a2, a3;
            ldm_x4(a0, a1, a2, a3, pBase + (uint32_t)(ksb * 32));
#pragma unroll
            for (int j = 0; j < 3; j++) {
                const int nt = wn + 4*j;
                if (nt < 10) {
                    const uint32_t b0 = Vt[(nt*8 + g)*VTW + ksb*8 + c];
                    const uint32_t b1 = Vt[(nt*8 + g)*VTW + ksb*8 + c + 4];
                    mma_f16(o[j], a0, a1, a2, a3, b0, b1);
                }
            }
        }

#pragma unroll
        for (int j = 0; j < 3; j++) {
            const int nt = wn + 4*j;
            if (nt < 10) {
#pragma unroll
                for (int r = 0; r < 4; r++) {
                    const int t = t0 + mr + g + ((r >= 2) ? 8 : 0);
                    const int f = nt*8 + 2*c + (r & 1);
                    if (t < T_ && f < HS_)
                        g_atth[((size_t)(b*T_ + t))*E_ + h*HS_ + f] = __float2half(o[j][r]);
                }
            }
        }
        named_bar(barid, 128);
    }
}

// ---------------------------------------------------------------------------
extern "C" void kernel_launch(void* const* d_in, const int* in_sizes, int n_in,
                              void* d_out, int out_size)
{
    const float* x  = (const float*)d_in[0];
    const float* Wq = (const float*)d_in[1];
    const float* Wk = (const float*)d_in[2];
    const float* Wv = (const float*)d_in[3];
    const float* Wo = (const float*)d_in[4];
    const float* bo = (const float*)d_in[5];
    float* out = (float*)d_out;

    cudaFuncSetAttribute(gemm_f16<0>, cudaFuncAttributeMaxDynamicSharedMemorySize, GSMEM);
    cudaFuncSetAttribute(gemm_f16<1>, cudaFuncAttributeMaxDynamicSharedMemorySize, GSMEM);

    const int att_smem = ATT_WORDS * (int)sizeof(uint32_t);
    cudaFuncSetAttribute(attn_mma, cudaFuncAttributeMaxDynamicSharedMemorySize, att_smem);

    // prep: fp32 -> padded fp16
    cvt_x<<<(M_*(XP/2) + 255)/256, 256>>>(x);
    cvt_w<<<((1752+E_)*(XP/2) + 255)/256, 256>>>(Wq, Wk, Wv, Wo);

    // QKV projection
    gemm_f16<0><<<dim3(14, 400), 256, GSMEM>>>(nullptr, nullptr);

    // attention
    attn_mma<<<BH_, 512, att_smem>>>();

    // output projection
    gemm_f16<1><<<dim3(5, 400), 256, GSMEM>>>(bo, out);
}

// round 13
// speedup vs baseline: 2.1649x; 1.0754x over previous
#include <cuda_runtime.h>
#include <cuda_fp16.h>
#include <math.h>
#include <stdint.h>

// Problem constants
#define B_  256
#define T_  200
#define E_  584
#define H_  8
#define HS_ 73
#define HSP 74           // padded head stride (halves)
#define XP  592          // padded fp16 row stride for x / weights (16B multiple)
#define BH_ (B_*H_)      // 2048
#define M_  (B_*T_)      // 51200

// Scratch (allocation-free rule: __device__ globals; zero-init at load)
__device__ __half g_q[BH_*T_*HSP + 32];
__device__ __half g_k[BH_*T_*HSP + 32];
__device__ __half g_v[BH_*T_*HSP + 32];
__device__ __half g_atth[M_*E_ + 32];
__device__ __half g_xh[(size_t)M_*XP];
__device__ __half g_wh[1752*XP];      // Wq|Wk|Wv rows stacked
__device__ __half g_woh[E_*XP];

__device__ __forceinline__ uint32_t f2h2(float lo, float hi) {
    __half2 h = __floats2half2_rn(lo, hi);
    return *reinterpret_cast<uint32_t*>(&h);
}

__device__ __forceinline__ void mma_f16(float c[4],
                                        uint32_t a0, uint32_t a1, uint32_t a2, uint32_t a3,
                                        uint32_t b0, uint32_t b1) {
    asm volatile(
        "mma.sync.aligned.m16n8k16.row.col.f32.f16.f16.f32 "
        "{%0,%1,%2,%3}, {%4,%5,%6,%7}, {%8,%9}, {%0,%1,%2,%3};"
        : "+f"(c[0]), "+f"(c[1]), "+f"(c[2]), "+f"(c[3])
        : "r"(a0), "r"(a1), "r"(a2), "r"(a3), "r"(b0), "r"(b1));
}

__device__ __forceinline__ void ldm_x4(uint32_t& r0, uint32_t& r1,
                                       uint32_t& r2, uint32_t& r3, uint32_t a) {
    asm volatile("ldmatrix.sync.aligned.m8n8.x4.shared.b16 {%0,%1,%2,%3}, [%4];"
                 : "=r"(r0), "=r"(r1), "=r"(r2), "=r"(r3) : "r"(a));
}

__device__ __forceinline__ uint32_t s2u(const void* p) {
    return (uint32_t)__cvta_generic_to_shared(p);
}
__device__ __forceinline__ void cp16(uint32_t d, const void* s, bool v) {
    asm volatile("cp.async.ca.shared.global [%0], [%1], 16, %2;"
                 :: "r"(d), "l"(s), "r"(v ? 16 : 0));
}
__device__ __forceinline__ void cp_commit() { asm volatile("cp.async.commit_group;"); }
__device__ __forceinline__ void cp_wait1()  { asm volatile("cp.async.wait_group 1;"); }
__device__ __forceinline__ void named_bar(int id, int cnt) {
    asm volatile("bar.sync %0, %1;" :: "r"(id), "r"(cnt) : "memory");
}

// ---------------------------------------------------------------------------
// Conversion prep kernels (fp32 -> padded fp16)
// ---------------------------------------------------------------------------
__global__ void cvt_x(const float* __restrict__ x) {
    const int W = XP / 2;   // 296 words per row
    int i = blockIdx.x * 256 + threadIdx.x;
    if (i >= M_ * W) return;
    int m = i / W, c2 = (i - m * W) * 2;
    float lo = (c2     < E_) ? x[(size_t)m * E_ + c2]     : 0.f;
    float hi = (c2 + 1 < E_) ? x[(size_t)m * E_ + c2 + 1] : 0.f;
    reinterpret_cast<uint32_t*>(g_xh)[i] = f2h2(lo, hi);
}

__global__ void cvt_w(const float* __restrict__ Wq, const float* __restrict__ Wk,
                      const float* __restrict__ Wv, const float* __restrict__ Wo) {
    const int W = XP / 2;
    int i = blockIdx.x * 256 + threadIdx.x;
    if (i >= (1752 + E_) * W) return;
    int row = i / W, c2 = (i - row * W) * 2;
    const float* src;
    uint32_t* dst;
    int r;
    if (row < 1752) {
        int s = row / E_;
        r = row - s * E_;
        src = (s == 0) ? Wq : ((s == 1) ? Wk : Wv);
        dst = reinterpret_cast<uint32_t*>(g_wh) + (size_t)row * W;
    } else {
        r = row - 1752;
        src = Wo;
        dst = reinterpret_cast<uint32_t*>(g_woh) + (size_t)r * W;
    }
    float lo = (c2     < E_) ? src[(size_t)r * E_ + c2]     : 0.f;
    float hi = (c2 + 1 < E_) ? src[(size_t)r * E_ + c2 + 1] : 0.f;
    dst[i - row * W] = f2h2(lo, hi);
}

// ---------------------------------------------------------------------------
// FP16 GEMM with cp.async 3-stage pipeline (R12, unchanged)
// ---------------------------------------------------------------------------
#define ROWPW  20
#define BK     32
#define STAGES 3
#define NSTG   19
#define TWW    (128*ROWPW)
#define GSMEM  (STAGES*2*TWW*4)

template<int MODE>
__global__ __launch_bounds__(256, 2)
void gemm_f16(const float* __restrict__ bias, float* __restrict__ out)
{
    extern __shared__ uint32_t gsm[];
    uint32_t* As = gsm;               // [STAGES][TWW]
    uint32_t* Bs = gsm + STAGES*TWW;  // [STAGES][TWW]

    const __half* A = (MODE == 0) ? g_xh  : g_atth;
    const __half* Bm = (MODE == 0) ? g_wh : g_woh;
    const int strideA = (MODE == 0) ? XP : E_;
    const int availA  = (MODE == 0) ? XP : E_;
    const int Ntot    = (MODE == 0) ? 1752 : E_;

    const int tid  = threadIdx.x;
    const int lane = tid & 31;
    const int w    = tid >> 5;
    const int g    = lane >> 2;
    const int c    = lane & 3;
    const int wm   = w & 3;
    const int wn   = w >> 2;

    const int m0 = blockIdx.y * 128;
    const int n0 = blockIdx.x * 128;

    float acc[2][8][4];
#pragma unroll
    for (int mi = 0; mi < 2; mi++)
#pragma unroll
        for (int ni = 0; ni < 8; ni++)
#pragma unroll
            for (int r = 0; r < 4; r++) acc[mi][ni][r] = 0.f;

    const int row  = tid >> 1;
    const int kseg = (tid & 1) * 16;

    const __half* aptr = A + (size_t)(m0 + row) * strideA + kseg;
    const int gn = n0 + row;
    const bool bval = gn < Ntot;
    const __half* bptr = Bm + (size_t)(bval ? gn : 0) * XP + kseg;

    const uint32_t a_s0 = s2u(&As[row * ROWPW + (tid & 1) * 8]);
    const uint32_t b_s0 = s2u(&Bs[row * ROWPW + (tid & 1) * 8]);
    const uint32_t stage_bytes = TWW * 4;

    auto issue = [&](int s) {
        if (s < NSTG) {
            const int kb = s * BK;
            const int slot = s % STAGES;
            const uint32_t ad = a_s0 + slot * stage_bytes;
            const uint32_t bd = b_s0 + slot * stage_bytes;
            const int kk0 = kb + kseg;
            cp16(ad,      aptr + kb,     kk0 + 8  <= availA);
            cp16(ad + 16, aptr + kb + 8, kk0 + 16 <= availA);
            cp16(bd,      bptr + kb,     bval && (kk0 + 8  <= XP));
            cp16(bd + 16, bptr + kb + 8, bval && (kk0 + 16 <= XP));
        }
        cp_commit();
    };

    const int lr = lane & 15, lh = lane >> 4;
    uint32_t aAdr[2], bAdr[4];
#pragma unroll
    for (int mi = 0; mi < 2; mi++)
        aAdr[mi] = s2u(&As[0]) + (uint32_t)(((wm*32 + mi*16 + lr) * ROWPW + lh*4) * 4);
#pragma unroll
    for (int np = 0; np < 4; np++)
        bAdr[np] = s2u(&Bs[0]) + (uint32_t)(((wn*64 + np*16 + lr) * ROWPW + lh*4) * 4);

    issue(0);
    issue(1);

#pragma unroll 1
    for (int s = 0; s < NSTG; s++) {
        cp_wait1();
        __syncthreads();
        issue(s + 2);

        const uint32_t kb = (uint32_t)(s % STAGES) * stage_bytes;
#pragma unroll
        for (int t16 = 0; t16 < 2; t16++) {
            const uint32_t ko = kb + t16 * 32;
            uint32_t a[2][4], bm[4][4];
#pragma unroll
            for (int mi = 0; mi < 2; mi++)
                ldm_x4(a[mi][0], a[mi][1], a[mi][2], a[mi][3], aAdr[mi] + ko);
#pragma unroll
            for (int np = 0; np < 4; np++)
                ldm_x4(bm[np][0], bm[np][1], bm[np][2], bm[np][3], bAdr[np] + ko);
#pragma unroll
            for (int mi = 0; mi < 2; mi++)
#pragma unroll
                for (int np = 0; np < 4; np++) {
                    mma_f16(acc[mi][2*np],   a[mi][0], a[mi][1], a[mi][2], a[mi][3],
                            bm[np][0], bm[np][2]);
                    mma_f16(acc[mi][2*np+1], a[mi][0], a[mi][1], a[mi][2], a[mi][3],
                            bm[np][1], bm[np][3]);
                }
        }
    }

    const float scale = rsqrtf((float)E_);
#pragma unroll
    for (int mi = 0; mi < 2; mi++) {
#pragma unroll
        for (int ni = 0; ni < 8; ni++) {
#pragma unroll
            for (int r = 0; r < 4; r++) {
                const int m = m0 + wm * 32 + mi * 16 + g + ((r >= 2) ? 8 : 0);
                const int n = n0 + wn * 64 + ni * 8 + 2 * c + (r & 1);
                const float v = acc[mi][ni][r];
                if (MODE == 0) {
                    if (n < 3 * E_) {
                        const int sidx = n / E_;
                        const int l    = n - sidx * E_;
                        const int hh   = l / HS_;
                        const int f    = l - hh * HS_;
                        const int bb   = m / T_;
                        const int t    = m - bb * T_;
                        __half* dst = (sidx == 0) ? g_q : ((sidx == 1) ? g_k : g_v);
                        const float vv = (sidx == 0) ? v * scale : v;
                        dst[((size_t)(bb * H_ + hh) * T_ + t) * HSP + f] = __float2half(vv);
                    }
                } else {
                    if (n < E_)
                        out[(size_t)m * E_ + n] = v + bias[n];
                }
            }
        }
    }
}

// ---------------------------------------------------------------------------
// FP16 attention — R12 structure, now 2 CTAs/SM via __launch_bounds__(512, 2)
// (regs capped at 64/thread; smem 100.9 KB x 2 = 201.7 KB fits in 227 KB)
// ---------------------------------------------------------------------------
#define KSW 44
#define VTW 108
#define PTW 108
#define ATT_WORDS (208*KSW + 80*VTW + 64*PTW + 512)

__global__ __launch_bounds__(512, 2)
void attn_mma()
{
    extern __shared__ uint32_t smu[];
    uint32_t* Ks = smu;                    // [208][44]
    uint32_t* Vt = Ks + 208*KSW;           // [80][108]
    uint32_t* Pt = Vt + 80*VTW;            // [64][108]
    float* pmax  = (float*)(Pt + 64*PTW);  // [64][4]
    float* psum  = pmax + 256;             // [64][4]

    const int bh   = blockIdx.x;
    const int tid  = threadIdx.x;
    const int lane = tid & 31;
    const int w    = tid >> 5;
    const int g    = lane >> 2;
    const int c    = lane & 3;
    const int wm   = w & 3;
    const int wn   = w >> 2;
    const int b    = bh / H_;
    const int h    = bh - b * H_;
    const int barid = 1 + wm;

    const __half* qg = g_q + (size_t)bh * T_ * HSP;
    const __half* kg = g_k + (size_t)bh * T_ * HSP;
    const __half* vg = g_v + (size_t)bh * T_ * HSP;

    for (int i = tid; i < 208*40; i += 512) {
        const int s = i / 40, f2 = i - s * 40;
        uint32_t val = 0;
        if (s < T_) {
            if (2*f2 + 1 < HS_) val = *(const uint32_t*)(kg + (size_t)s*HSP + 2*f2);
            else if (2*f2 < HS_) val = (uint32_t)__half_as_ushort(kg[(size_t)s*HSP + 2*f2]);
        }
        Ks[s*KSW + f2] = val;
    }
    for (int i = tid; i < 80*104; i += 512) {
        const int f = i / 104, s2 = i - f * 104;
        __half lo = (2*s2   < T_ && f < HS_) ? vg[(size_t)(2*s2  )*HSP + f] : __ushort_as_half((unsigned short)0);
        __half hi = (2*s2+1 < T_ && f < HS_) ? vg[(size_t)(2*s2+1)*HSP + f] : __ushort_as_half((unsigned short)0);
        __half2 p = __halves2half2(lo, hi);
        Vt[f*VTW + s2] = *reinterpret_cast<uint32_t*>(&p);
    }
    __syncthreads();

    const int mr = wm * 16;
    const int rq_lo = mr + g;
    const int rq_hi = mr + g + 8;

    const int lr = lane & 15, lh = lane >> 4;
    const uint32_t kBase = s2u(Ks) + (uint32_t)((lr * KSW + lh * 4) * 4);
    const uint32_t pBase = s2u(Pt) + (uint32_t)(((mr + lr) * PTW + lh * 4) * 4);

#pragma unroll 1
    for (int t0 = 0; t0 < T_; t0 += 64) {
        const int thi = t0 + mr + 15;

        const int row_lo = (t0 + rq_lo < T_) ? (t0 + rq_lo) : (T_ - 1);
        const int row_hi = (t0 + rq_hi < T_) ? (t0 + rq_hi) : (T_ - 1);
        const __half* qlo = qg + (size_t)row_lo * HSP;
        const __half* qhi = qg + (size_t)row_hi * HSP;

        float acc[4][2][4];
#pragma unroll
        for (int u = 0; u < 4; u++)
#pragma unroll
            for (int e = 0; e < 2; e++)
#pragma unroll
                for (int r = 0; r < 4; r++) acc[u][e][r] = 0.f;

#pragma unroll
        for (int ks = 0; ks < 80; ks += 16) {
            const int k0 = ks + 2*c;
            const int k1 = k0 + 8;
            const uint32_t a0 = *(const uint32_t*)(qlo + k0);
            const uint32_t a1 = *(const uint32_t*)(qhi + k0);
            const uint32_t a2 = *(const uint32_t*)(qlo + k1);
            const uint32_t a3 = *(const uint32_t*)(qhi + k1);
#pragma unroll
            for (int u = 0; u < 4; u++) {
                const int chunk = 4*u + wn;
                const int cb = chunk * 16;
                if (chunk < 13 && cb <= thi) {
                    uint32_t b0, b1, b2, b3;
                    ldm_x4(b0, b1, b2, b3, kBase + (uint32_t)(cb * (KSW*4) + ks * 2));
                    mma_f16(acc[u][0], a0, a1, a2, a3, b0, b2);
                    mma_f16(acc[u][1], a0, a1, a2, a3, b1, b3);
                }
            }
        }

        const int t_lo = t0 + rq_lo;
        const int t_hi = t0 + rq_hi;

        float mlo = -1e30f, mhi = -1e30f;
#pragma unroll
        for (int u = 0; u < 4; u++)
#pragma unroll
            for (int e = 0; e < 2; e++) {
                const int s0 = (4*u + wn)*16 + e*8 + 2*c;
                const int s1 = s0 + 1;
                if ((s0 <= t_lo) && (s0 < T_) && (t_lo < T_)) mlo = fmaxf(mlo, acc[u][e][0]);
                if ((s1 <= t_lo) && (s1 < T_) && (t_lo < T_)) mlo = fmaxf(mlo, acc[u][e][1]);
                if ((s0 <= t_hi) && (s0 < T_) && (t_hi < T_)) mhi = fmaxf(mhi, acc[u][e][2]);
                if ((s1 <= t_hi) && (s1 < T_) && (t_hi < T_)) mhi = fmaxf(mhi, acc[u][e][3]);
            }
#pragma unroll
        for (int off = 1; off <= 2; off <<= 1) {
            mlo = fmaxf(mlo, __shfl_xor_sync(0xffffffffu, mlo, off));
            mhi = fmaxf(mhi, __shfl_xor_sync(0xffffffffu, mhi, off));
        }
        if (c == 0) {
            pmax[rq_lo*4 + wn] = mlo;
            pmax[rq_hi*4 + wn] = mhi;
        }
        named_bar(barid, 128);
        const float gmlo = fmaxf(fmaxf(pmax[rq_lo*4], pmax[rq_lo*4+1]),
                                 fmaxf(pmax[rq_lo*4+2], pmax[rq_lo*4+3]));
        const float gmhi = fmaxf(fmaxf(pmax[rq_hi*4], pmax[rq_hi*4+1]),
                                 fmaxf(pmax[rq_hi*4+2], pmax[rq_hi*4+3]));

        float slo = 0.f, shi = 0.f;
#pragma unroll
        for (int u = 0; u < 4; u++)
#pragma unroll
            for (int e = 0; e < 2; e++) {
                const int s0 = (4*u + wn)*16 + e*8 + 2*c;
                const int s1 = s0 + 1;
                const bool ok0l = (s0 <= t_lo) && (s0 < T_) && (t_lo < T_);
                const bool ok1l = (s1 <= t_lo) && (s1 < T_) && (t_lo < T_);
                const bool ok0h = (s0 <= t_hi) && (s0 < T_) && (t_hi < T_);
                const bool ok1h = (s1 <= t_hi) && (s1 < T_) && (t_hi < T_);
                float e0 = ok0l ? __expf(acc[u][e][0] - gmlo) : 0.f;
                float e1 = ok1l ? __expf(acc[u][e][1] - gmlo) : 0.f;
                float e2 = ok0h ? __expf(acc[u][e][2] - gmhi) : 0.f;
                float e3 = ok1h ? __expf(acc[u][e][3] - gmhi) : 0.f;
                acc[u][e][0] = e0; acc[u][e][1] = e1;
                acc[u][e][2] = e2; acc[u][e][3] = e3;
                slo += e0 + e1;  shi += e2 + e3;
            }
#pragma unroll
        for (int off = 1; off <= 2; off <<= 1) {
            slo += __shfl_xor_sync(0xffffffffu, slo, off);
            shi += __shfl_xor_sync(0xffffffffu, shi, off);
        }
        if (c == 0) {
            psum[rq_lo*4 + wn] = slo;
            psum[rq_hi*4 + wn] = shi;
        }
        named_bar(barid, 128);
        const float tlo  = psum[rq_lo*4] + psum[rq_lo*4+1] + psum[rq_lo*4+2] + psum[rq_lo*4+3];
        const float thi2 = psum[rq_hi*4] + psum[rq_hi*4+1] + psum[rq_hi*4+2] + psum[rq_hi*4+3];
        const float rlo = (tlo  > 0.f) ? (1.f / tlo)  : 0.f;
        const float rhi = (thi2 > 0.f) ? (1.f / thi2) : 0.f;

#pragma unroll
        for (int u = 0; u < 4; u++) {
            const int chunk = 4*u + wn;
            if (chunk < 13) {
#pragma unroll
                for (int e = 0; e < 2; e++) {
                    const int cw = chunk*8 + e*4 + c;
                    Pt[rq_lo*PTW + cw] = f2h2(acc[u][e][0]*rlo, acc[u][e][1]*rlo);
                    Pt[rq_hi*PTW + cw] = f2h2(acc[u][e][2]*rhi, acc[u][e][3]*rhi);
                }
            }
        }
        named_bar(barid, 128);

        float o[3][4];
#pragma unroll
        for (int j = 0; j < 3; j++)
#pragma unroll
            for (int r = 0; r < 4; r++) o[j][r] = 0.f;

        const int kcap    = (thi < T_-1) ? thi : (T_-1);
        const int ksb_end = kcap >> 4;
#pragma unroll 1
        for (int ksb = 0; ksb <= ksb_end; ksb++) {
            uint32_t a0, a1, a2, a3;
            ldm_x4(a0, a1, a2, a3, pBase + (uint32_t)(ksb * 32));
#pragma unroll
            for (int j = 0; j < 3; j++) {
                const int nt = wn + 4*j;
                if (nt < 10) {
                    const uint32_t b0 = Vt[(nt*8 + g)*VTW + ksb*8 + c];
                    const uint32_t b1 = Vt[(nt*8 + g)*VTW + ksb*8 + c + 4];
                    mma_f16(o[j], a0, a1, a2, a3, b0, b1);
                }
            }
        }

#pragma unroll
        for (int j = 0; j < 3; j++) {
            const int nt = wn + 4*j;
            if (nt < 10) {
#pragma unroll
                for (int r = 0; r < 4; r++) {
                    const int t = t0 + mr + g + ((r >= 2) ? 8 : 0);
                    const int f = nt*8 + 2*c + (r & 1);
                    if (t < T_ && f < HS_)
                        g_atth[((size_t)(b*T_ + t))*E_ + h*HS_ + f] = __float2half(o[j][r]);
                }
            }
        }
        named_bar(barid, 128);
    }
}

// ---------------------------------------------------------------------------
extern "C" void kernel_launch(void* const* d_in, const int* in_sizes, int n_in,
                              void* d_out, int out_size)
{
    const float* x  = (const float*)d_in[0];
    const float* Wq = (const float*)d_in[1];
    const float* Wk = (const float*)d_in[2];
    const float* Wv = (const float*)d_in[3];
    const float* Wo = (const float*)d_in[4];
    const float* bo = (const float*)d_in[5];
    float* out = (float*)d_out;

    cudaFuncSetAttribute(gemm_f16<0>, cudaFuncAttributeMaxDynamicSharedMemorySize, GSMEM);
    cudaFuncSetAttribute(gemm_f16<1>, cudaFuncAttributeMaxDynamicSharedMemorySize, GSMEM);

    const int att_smem = ATT_WORDS * (int)sizeof(uint32_t);
    cudaFuncSetAttribute(attn_mma, cudaFuncAttributeMaxDynamicSharedMemorySize, att_smem);

    // prep: fp32 -> padded fp16
    cvt_x<<<(M_*(XP/2) + 255)/256, 256>>>(x);
    cvt_w<<<((1752+E_)*(XP/2) + 255)/256, 256>>>(Wq, Wk, Wv, Wo);

    // QKV projection
    gemm_f16<0><<<dim3(14, 400), 256, GSMEM>>>(nullptr, nullptr);

    // attention (2 CTAs/SM)
    attn_mma<<<BH_, 512, att_smem>>>();

    // output projection
    gemm_f16<1><<<dim3(5, 400), 256, GSMEM>>>(bo, out);
}

// round 15
// speedup vs baseline: 2.1890x; 1.0111x over previous
#include <cuda_runtime.h>
#include <cuda_fp16.h>
#include <math.h>
#include <stdint.h>

// Problem constants
#define B_  256
#define T_  200
#define E_  584
#define H_  8
#define HS_ 73
#define HSP 74           // padded head stride (halves)
#define XP  592          // padded fp16 row stride for x / weights (16B multiple)
#define BH_ (B_*H_)      // 2048
#define M_  (B_*T_)      // 51200

// Scratch (allocation-free rule: __device__ globals; zero-init at load)
__device__ __half g_q[BH_*T_*HSP + 32];
__device__ __half g_k[BH_*T_*HSP + 32];
__device__ __half g_v[BH_*T_*HSP + 32];
__device__ __half g_atth[M_*E_ + 32];
__device__ __half g_xh[(size_t)M_*XP];
__device__ __half g_wh[1752*XP];      // Wq|Wk|Wv rows stacked
__device__ __half g_woh[E_*XP];

__device__ __forceinline__ uint32_t f2h2(float lo, float hi) {
    __half2 h = __floats2half2_rn(lo, hi);
    return *reinterpret_cast<uint32_t*>(&h);
}

__device__ __forceinline__ void mma_f16(float c[4],
                                        uint32_t a0, uint32_t a1, uint32_t a2, uint32_t a3,
                                        uint32_t b0, uint32_t b1) {
    asm volatile(
        "mma.sync.aligned.m16n8k16.row.col.f32.f16.f16.f32 "
        "{%0,%1,%2,%3}, {%4,%5,%6,%7}, {%8,%9}, {%0,%1,%2,%3};"
        : "+f"(c[0]), "+f"(c[1]), "+f"(c[2]), "+f"(c[3])
        : "r"(a0), "r"(a1), "r"(a2), "r"(a3), "r"(b0), "r"(b1));
}

__device__ __forceinline__ void ldm_x4(uint32_t& r0, uint32_t& r1,
                                       uint32_t& r2, uint32_t& r3, uint32_t a) {
    asm volatile("ldmatrix.sync.aligned.m8n8.x4.shared.b16 {%0,%1,%2,%3}, [%4];"
                 : "=r"(r0), "=r"(r1), "=r"(r2), "=r"(r3) : "r"(a));
}

__device__ __forceinline__ uint32_t s2u(const void* p) {
    return (uint32_t)__cvta_generic_to_shared(p);
}
__device__ __forceinline__ void cp16(uint32_t d, const void* s, bool v) {
    asm volatile("cp.async.ca.shared.global [%0], [%1], 16, %2;"
                 :: "r"(d), "l"(s), "r"(v ? 16 : 0));
}
__device__ __forceinline__ void cp_commit() { asm volatile("cp.async.commit_group;"); }
__device__ __forceinline__ void cp_wait2()  { asm volatile("cp.async.wait_group 2;"); }
__device__ __forceinline__ void named_bar(int id, int cnt) {
    asm volatile("bar.sync %0, %1;" :: "r"(id), "r"(cnt) : "memory");
}

// ---------------------------------------------------------------------------
// Conversion prep kernels (fp32 -> padded fp16)
// ---------------------------------------------------------------------------
__global__ void cvt_x(const float* __restrict__ x) {
    const int W = XP / 2;
    int i = blockIdx.x * 256 + threadIdx.x;
    if (i >= M_ * W) return;
    int m = i / W, c2 = (i - m * W) * 2;
    float lo = (c2     < E_) ? x[(size_t)m * E_ + c2]     : 0.f;
    float hi = (c2 + 1 < E_) ? x[(size_t)m * E_ + c2 + 1] : 0.f;
    reinterpret_cast<uint32_t*>(g_xh)[i] = f2h2(lo, hi);
}

__global__ void cvt_w(const float* __restrict__ Wq, const float* __restrict__ Wk,
                      const float* __restrict__ Wv, const float* __restrict__ Wo) {
    const int W = XP / 2;
    int i = blockIdx.x * 256 + threadIdx.x;
    if (i >= (1752 + E_) * W) return;
    int row = i / W, c2 = (i - row * W) * 2;
    const float* src;
    uint32_t* dst;
    int r;
    if (row < 1752) {
        int s = row / E_;
        r = row - s * E_;
        src = (s == 0) ? Wq : ((s == 1) ? Wk : Wv);
        dst = reinterpret_cast<uint32_t*>(g_wh) + (size_t)row * W;
    } else {
        r = row - 1752;
        src = Wo;
        dst = reinterpret_cast<uint32_t*>(g_woh) + (size_t)r * W;
    }
    float lo = (c2     < E_) ? src[(size_t)r * E_ + c2]     : 0.f;
    float hi = (c2 + 1 < E_) ? src[(size_t)r * E_ + c2 + 1] : 0.f;
    dst[i - row * W] = f2h2(lo, hi);
}

// ---------------------------------------------------------------------------
// FP16 GEMM with cp.async 4-stage pipeline:  C[m,n] = sum_k A[m,k]*B[n,k]
// CTA 128x128, BK=32 (halves), 256 threads (8 warps, 4m x 2n), warp 32x64.
// ---------------------------------------------------------------------------
#define ROWPW  20
#define BK     32
#define STAGES 4
#define NSTG   19
#define TWW    (128*ROWPW)
#define GSMEM  (STAGES*2*TWW*4)

template<int MODE>
__global__ __launch_bounds__(256, 2)
void gemm_f16(const float* __restrict__ bias, float* __restrict__ out)
{
    extern __shared__ uint32_t gsm[];
    uint32_t* As = gsm;               // [STAGES][TWW]
    uint32_t* Bs = gsm + STAGES*TWW;  // [STAGES][TWW]

    const __half* A = (MODE == 0) ? g_xh  : g_atth;
    const __half* Bm = (MODE == 0) ? g_wh : g_woh;
    const int strideA = (MODE == 0) ? XP : E_;
    const int availA  = (MODE == 0) ? XP : E_;
    const int Ntot    = (MODE == 0) ? 1752 : E_;

    const int tid  = threadIdx.x;
    const int lane = tid & 31;
    const int w    = tid >> 5;
    const int g    = lane >> 2;
    const int c    = lane & 3;
    const int wm   = w & 3;
    const int wn   = w >> 2;

    const int m0 = blockIdx.y * 128;
    const int n0 = blockIdx.x * 128;

    float acc[2][8][4];
#pragma unroll
    for (int mi = 0; mi < 2; mi++)
#pragma unroll
        for (int ni = 0; ni < 8; ni++)
#pragma unroll
            for (int r = 0; r < 4; r++) acc[mi][ni][r] = 0.f;

    const int row  = tid >> 1;
    const int kseg = (tid & 1) * 16;

    const __half* aptr = A + (size_t)(m0 + row) * strideA + kseg;
    const int gn = n0 + row;
    const bool bval = gn < Ntot;
    const __half* bptr = Bm + (size_t)(bval ? gn : 0) * XP + kseg;

    const uint32_t a_s0 = s2u(&As[row * ROWPW + (tid & 1) * 8]);
    const uint32_t b_s0 = s2u(&Bs[row * ROWPW + (tid & 1) * 8]);
    const uint32_t stage_bytes = TWW * 4;

    auto issue = [&](int s) {
        if (s < NSTG) {
            const int kb = s * BK;
            const int slot = s % STAGES;
            const uint32_t ad = a_s0 + slot * stage_bytes;
            const uint32_t bd = b_s0 + slot * stage_bytes;
            const int kk0 = kb + kseg;
            cp16(ad,      aptr + kb,     kk0 + 8  <= availA);
            cp16(ad + 16, aptr + kb + 8, kk0 + 16 <= availA);
            cp16(bd,      bptr + kb,     bval && (kk0 + 8  <= XP));
            cp16(bd + 16, bptr + kb + 8, bval && (kk0 + 16 <= XP));
        }
        cp_commit();
    };

    const int lr = lane & 15, lh = lane >> 4;
    uint32_t aAdr[2], bAdr[4];
#pragma unroll
    for (int mi = 0; mi < 2; mi++)
        aAdr[mi] = s2u(&As[0]) + (uint32_t)(((wm*32 + mi*16 + lr) * ROWPW + lh*4) * 4);
#pragma unroll
    for (int np = 0; np < 4; np++)
        bAdr[np] = s2u(&Bs[0]) + (uint32_t)(((wn*64 + np*16 + lr) * ROWPW + lh*4) * 4);

    issue(0);
    issue(1);
    issue(2);

#pragma unroll 1
    for (int s = 0; s < NSTG; s++) {
        cp_wait2();
        __syncthreads();
        issue(s + 3);

        const uint32_t kb = (uint32_t)(s % STAGES) * stage_bytes;
#pragma unroll
        for (int t16 = 0; t16 < 2; t16++) {
            const uint32_t ko = kb + t16 * 32;
            uint32_t a[2][4], bm[4][4];
#pragma unroll
            for (int mi = 0; mi < 2; mi++)
                ldm_x4(a[mi][0], a[mi][1], a[mi][2], a[mi][3], aAdr[mi] + ko);
#pragma unroll
            for (int np = 0; np < 4; np++)
                ldm_x4(bm[np][0], bm[np][1], bm[np][2], bm[np][3], bAdr[np] + ko);
#pragma unroll
            for (int mi = 0; mi < 2; mi++)
#pragma unroll
                for (int np = 0; np < 4; np++) {
                    mma_f16(acc[mi][2*np],   a[mi][0], a[mi][1], a[mi][2], a[mi][3],
                            bm[np][0], bm[np][2]);
                    mma_f16(acc[mi][2*np+1], a[mi][0], a[mi][1], a[mi][2], a[mi][3],
                            bm[np][1], bm[np][3]);
                }
        }
    }

    const float scale = rsqrtf((float)E_);
#pragma unroll
    for (int mi = 0; mi < 2; mi++) {
#pragma unroll
        for (int ni = 0; ni < 8; ni++) {
#pragma unroll
            for (int r = 0; r < 4; r++) {
                const int m = m0 + wm * 32 + mi * 16 + g + ((r >= 2) ? 8 : 0);
                const int n = n0 + wn * 64 + ni * 8 + 2 * c + (r & 1);
                const float v = acc[mi][ni][r];
                if (MODE == 0) {
                    if (n < 3 * E_) {
                        const int sidx = n / E_;
                        const int l    = n - sidx * E_;
                        const int hh   = l / HS_;
                        const int f    = l - hh * HS_;
                        const int bb   = m / T_;
                        const int t    = m - bb * T_;
                        __half* dst = (sidx == 0) ? g_q : ((sidx == 1) ? g_k : g_v);
                        const float vv = (sidx == 0) ? v * scale : v;
                        dst[((size_t)(bb * H_ + hh) * T_ + t) * HSP + f] = __float2half(vv);
                    }
                } else {
                    if (n < E_)
                        out[(size_t)m * E_ + n] = v + bias[n];
                }
            }
        }
    }
}

// ---------------------------------------------------------------------------
// FP16 attention v5b: single-pass softmax, unnormalized P (guarded stores!),
// 1/sum folded into PV epilogue. 2 barriers per Q-tile. 512 thr, 2 CTAs/SM.
// ---------------------------------------------------------------------------
#define KSW 44
#define VTW 108
#define PTW 108
#define ATT_WORDS (208*KSW + 80*VTW + 64*PTW + 512)

__global__ __launch_bounds__(512, 2)
void attn_mma()
{
    extern __shared__ uint32_t smu[];
    uint32_t* Ks = smu;                    // [208][44]
    uint32_t* Vt = Ks + 208*KSW;           // [80][108]
    uint32_t* Pt = Vt + 80*VTW;            // [64][108]
    float* psum  = (float*)(Pt + 64*PTW);  // [64][4]

    const int bh   = blockIdx.x;
    const int tid  = threadIdx.x;
    const int lane = tid & 31;
    const int w    = tid >> 5;
    const int g    = lane >> 2;
    const int c    = lane & 3;
    const int wm   = w & 3;
    const int wn   = w >> 2;
    const int b    = bh / H_;
    const int h    = bh - b * H_;
    const int barid = 1 + wm;

    const __half* qg = g_q + (size_t)bh * T_ * HSP;
    const __half* kg = g_k + (size_t)bh * T_ * HSP;
    const __half* vg = g_v + (size_t)bh * T_ * HSP;

    for (int i = tid; i < 208*40; i += 512) {
        const int s = i / 40, f2 = i - s * 40;
        uint32_t val = 0;
        if (s < T_) {
            if (2*f2 + 1 < HS_) val = *(const uint32_t*)(kg + (size_t)s*HSP + 2*f2);
            else if (2*f2 < HS_) val = (uint32_t)__half_as_ushort(kg[(size_t)s*HSP + 2*f2]);
        }
        Ks[s*KSW + f2] = val;
    }
    for (int i = tid; i < 80*104; i += 512) {
        const int f = i / 104, s2 = i - f * 104;
        __half lo = (2*s2   < T_ && f < HS_) ? vg[(size_t)(2*s2  )*HSP + f] : __ushort_as_half((unsigned short)0);
        __half hi = (2*s2+1 < T_ && f < HS_) ? vg[(size_t)(2*s2+1)*HSP + f] : __ushort_as_half((unsigned short)0);
        __half2 p = __halves2half2(lo, hi);
        Vt[f*VTW + s2] = *reinterpret_cast<uint32_t*>(&p);
    }
    __syncthreads();

    const int mr = wm * 16;
    const int rq_lo = mr + g;
    const int rq_hi = mr + g + 8;

    const int lr = lane & 15, lh = lane >> 4;
    const uint32_t kBase = s2u(Ks) + (uint32_t)((lr * KSW + lh * 4) * 4);
    const uint32_t pBase = s2u(Pt) + (uint32_t)(((mr + lr) * PTW + lh * 4) * 4);

#pragma unroll 1
    for (int t0 = 0; t0 < T_; t0 += 64) {
        const int thi = t0 + mr + 15;

        const int row_lo = (t0 + rq_lo < T_) ? (t0 + rq_lo) : (T_ - 1);
        const int row_hi = (t0 + rq_hi < T_) ? (t0 + rq_hi) : (T_ - 1);
        const __half* qlo = qg + (size_t)row_lo * HSP;
        const __half* qhi = qg + (size_t)row_hi * HSP;

        float acc[4][2][4];
#pragma unroll
        for (int u = 0; u < 4; u++)
#pragma unroll
            for (int e = 0; e < 2; e++)
#pragma unroll
                for (int r = 0; r < 4; r++) acc[u][e][r] = 0.f;

        // ---- S = Q.K^T ------------------------------------------------------
#pragma unroll
        for (int ks = 0; ks < 80; ks += 16) {
            const int k0 = ks + 2*c;
            const int k1 = k0 + 8;
            const uint32_t a0 = *(const uint32_t*)(qlo + k0);
            const uint32_t a1 = *(const uint32_t*)(qhi + k0);
            const uint32_t a2 = *(const uint32_t*)(qlo + k1);
            const uint32_t a3 = *(const uint32_t*)(qhi + k1);
#pragma unroll
            for (int u = 0; u < 4; u++) {
                const int chunk = 4*u + wn;
                const int cb = chunk * 16;
                if (chunk < 13 && cb <= thi) {
                    uint32_t b0, b1, b2, b3;
                    ldm_x4(b0, b1, b2, b3, kBase + (uint32_t)(cb * (KSW*4) + ks * 2));
                    mma_f16(acc[u][0], a0, a1, a2, a3, b0, b2);
                    mma_f16(acc[u][1], a0, a1, a2, a3, b1, b3);
                }
            }
        }

        // ---- single-pass softmax: exp (scores bounded), sum, store unnorm P -
        const int t_lo = t0 + rq_lo;
        const int t_hi = t0 + rq_hi;

        float slo = 0.f, shi = 0.f;
#pragma unroll
        for (int u = 0; u < 4; u++) {
            const int chunk = 4*u + wn;
#pragma unroll
            for (int e = 0; e < 2; e++) {
                const int s0 = chunk*16 + e*8 + 2*c;
                const int s1 = s0 + 1;
                const bool ok0l = (s0 <= t_lo) && (s0 < T_) && (t_lo < T_);
                const bool ok1l = (s1 <= t_lo) && (s1 < T_) && (t_lo < T_);
                const bool ok0h = (s0 <= t_hi) && (s0 < T_) && (t_hi < T_);
                const bool ok1h = (s1 <= t_hi) && (s1 < T_) && (t_hi < T_);
                float e0 = ok0l ? __expf(acc[u][e][0]) : 0.f;
                float e1 = ok1l ? __expf(acc[u][e][1]) : 0.f;
                float e2 = ok0h ? __expf(acc[u][e][2]) : 0.f;
                float e3 = ok1h ? __expf(acc[u][e][3]) : 0.f;
                slo += e0 + e1;  shi += e2 + e3;
                if (chunk < 13) {      // GUARD: stay inside Pt row (PTW=108)
                    const int cw = chunk*8 + e*4 + c;
                    Pt[rq_lo*PTW + cw] = f2h2(e0, e1);
                    Pt[rq_hi*PTW + cw] = f2h2(e2, e3);
                }
            }
        }
#pragma unroll
        for (int off = 1; off <= 2; off <<= 1) {
            slo += __shfl_xor_sync(0xffffffffu, slo, off);
            shi += __shfl_xor_sync(0xffffffffu, shi, off);
        }
        if (c == 0) {
            psum[rq_lo*4 + wn] = slo;
            psum[rq_hi*4 + wn] = shi;
        }
        named_bar(barid, 128);
        const float tlo  = psum[rq_lo*4] + psum[rq_lo*4+1] + psum[rq_lo*4+2] + psum[rq_lo*4+3];
        const float thi2 = psum[rq_hi*4] + psum[rq_hi*4+1] + psum[rq_hi*4+2] + psum[rq_hi*4+3];
        const float rlo = (tlo  > 0.f) ? (1.f / tlo)  : 0.f;
        const float rhi = (thi2 > 0.f) ? (1.f / thi2) : 0.f;

        // ---- O = P.V (unnormalized P; scale at epilogue) ---------------------
        float o[3][4];
#pragma unroll
        for (int j = 0; j < 3; j++)
#pragma unroll
            for (int r = 0; r < 4; r++) o[j][r] = 0.f;

        const int kcap    = (thi < T_-1) ? thi : (T_-1);
        const int ksb_end = kcap >> 4;
#pragma unroll 1
        for (int ksb = 0; ksb <= ksb_end; ksb++) {
            uint32_t a0, a1, a2, a3;
            ldm_x4(a0, a1, a2, a3, pBase + (uint32_t)(ksb * 32));
#pragma unroll
            for (int j = 0; j < 3; j++) {
                const int nt = wn + 4*j;
                if (nt < 10) {
                    const uint32_t b0 = Vt[(nt*8 + g)*VTW + ksb*8 + c];
                    const uint32_t b1 = Vt[(nt*8 + g)*VTW + ksb*8 + c + 4];
                    mma_f16(o[j], a0, a1, a2, a3, b0, b1);
                }
            }
        }

#pragma unroll
        for (int j = 0; j < 3; j++) {
            const int nt = wn + 4*j;
            if (nt < 10) {
#pragma unroll
                for (int r = 0; r < 4; r++) {
                    const int t = t0 + mr + g + ((r >= 2) ? 8 : 0);
                    const int f = nt*8 + 2*c + (r & 1);
                    if (t < T_ && f < HS_) {
                        const float rr = (r < 2) ? rlo : rhi;
                        g_atth[((size_t)(b*T_ + t))*E_ + h*HS_ + f] = __float2half(o[j][r] * rr);
                    }
                }
            }
        }
        named_bar(barid, 128);   // Pt/psum safe to reuse next tile
    }
}

// ---------------------------------------------------------------------------
extern "C" void kernel_launch(void* const* d_in, const int* in_sizes, int n_in,
                              void* d_out, int out_size)
{
    const float* x  = (const float*)d_in[0];
    const float* Wq = (const float*)d_in[1];
    const float* Wk = (const float*)d_in[2];
    const float* Wv = (const float*)d_in[3];
    const float* Wo = (const float*)d_in[4];
    const float* bo = (const float*)d_in[5];
    float* out = (float*)d_out;

    cudaFuncSetAttribute(gemm_f16<0>, cudaFuncAttributeMaxDynamicSharedMemorySize, GSMEM);
    cudaFuncSetAttribute(gemm_f16<1>, cudaFuncAttributeMaxDynamicSharedMemorySize, GSMEM);

    const int att_smem = ATT_WORDS * (int)sizeof(uint32_t);
    cudaFuncSetAttribute(attn_mma, cudaFuncAttributeMaxDynamicSharedMemorySize, att_smem);

    // prep: fp32 -> padded fp16
    cvt_x<<<(M_*(XP/2) + 255)/256, 256>>>(x);
    cvt_w<<<((1752+E_)*(XP/2) + 255)/256, 256>>>(Wq, Wk, Wv, Wo);

    // QKV projection
    gemm_f16<0><<<dim3(14, 400), 256, GSMEM>>>(nullptr, nullptr);

    // attention (2 CTAs/SM)
    attn_mma<<<BH_, 512, att_smem>>>();

    // output projection
    gemm_f16<1><<<dim3(5, 400), 256, GSMEM>>>(bo, out);
}